// round 1
// baseline (speedup 1.0000x reference)
#include <cuda_runtime.h>
#include <math.h>

// Problem constants
constexpr int kB = 2, kT = 2048, kE = 1024, kH = 16, kD = 64;
constexpr float LAMBDA_INIT = 0.47071301834358415f;   // 0.8 - 0.6*exp(-0.6)
constexpr float SCALING     = 0.125f;                 // D^-0.5
constexpr float EPS         = 1e-5f;

// Scratch (device globals; allocation is forbidden)
__device__ float g_q1[kB * kH * kT * kD];
__device__ float g_k1[kB * kH * kT * kD];
__device__ float g_q2[kB * kH * kT * kD];
__device__ float g_k2[kB * kH * kT * kD];
__device__ float g_v [kB * kH * kT * kD];
__device__ float g_attn[kB * kT * kE];
__device__ float g_lambda;

// ---------------------------------------------------------------------------
// lambda = exp(sum lq1*lk1) - exp(sum lq2*lk2) + LAMBDA_INIT
// ---------------------------------------------------------------------------
__global__ void lambda_kernel(const float* __restrict__ lq1, const float* __restrict__ lk1,
                              const float* __restrict__ lq2, const float* __restrict__ lk2) {
    int l = threadIdx.x;
    float a = lq1[l] * lk1[l] + lq1[l + 32] * lk1[l + 32];
    float b = lq2[l] * lk2[l] + lq2[l + 32] * lk2[l + 32];
#pragma unroll
    for (int o = 16; o; o >>= 1) {
        a += __shfl_xor_sync(0xffffffffu, a, o);
        b += __shfl_xor_sync(0xffffffffu, b, o);
    }
    if (l == 0) g_lambda = expf(a) - expf(b) + LAMBDA_INIT;
}

// ---------------------------------------------------------------------------
// Tiled fp32 GEMM core:  C[m,n] = alpha * sum_k A[m,k] * W[n,k]
// M=4096, N=1024, K=1024.  128x128 tile, BK=16, 256 threads, 8x8 per thread.
// HEADOUT: store into [B,H,T,D] layout instead of row-major [M,N].
// ---------------------------------------------------------------------------
template <bool HEADOUT>
__device__ __forceinline__ void gemm_core(const float* __restrict__ A,
                                          const float* __restrict__ W,
                                          float* __restrict__ O, float alpha) {
    __shared__ float As[16][128];
    __shared__ float Bs[16][128];
    const int K = 1024;

    int tid = threadIdx.x;
    int tx = tid & 15, ty = tid >> 4;
    int m0 = blockIdx.y * 128, n0 = blockIdx.x * 128;

    float acc[8][8];
#pragma unroll
    for (int i = 0; i < 8; i++)
#pragma unroll
        for (int j = 0; j < 8; j++) acc[i][j] = 0.0f;

    int lrow = tid >> 2;         // 0..63
    int lk   = (tid & 3) * 4;    // 0,4,8,12
    const float* Ag = A + (size_t)(m0 + lrow) * K + lk;
    const float* Wg = W + (size_t)(n0 + lrow) * K + lk;

    for (int k0 = 0; k0 < K; k0 += 16) {
        float4 a0 = *(const float4*)(Ag + k0);
        float4 a1 = *(const float4*)(Ag + k0 + (size_t)64 * K);
        float4 b0 = *(const float4*)(Wg + k0);
        float4 b1 = *(const float4*)(Wg + k0 + (size_t)64 * K);
        __syncthreads();   // prior compute done before overwriting smem
        As[lk + 0][lrow] = a0.x; As[lk + 1][lrow] = a0.y;
        As[lk + 2][lrow] = a0.z; As[lk + 3][lrow] = a0.w;
        As[lk + 0][lrow + 64] = a1.x; As[lk + 1][lrow + 64] = a1.y;
        As[lk + 2][lrow + 64] = a1.z; As[lk + 3][lrow + 64] = a1.w;
        Bs[lk + 0][lrow] = b0.x; Bs[lk + 1][lrow] = b0.y;
        Bs[lk + 2][lrow] = b0.z; Bs[lk + 3][lrow] = b0.w;
        Bs[lk + 0][lrow + 64] = b1.x; Bs[lk + 1][lrow + 64] = b1.y;
        Bs[lk + 2][lrow + 64] = b1.z; Bs[lk + 3][lrow + 64] = b1.w;
        __syncthreads();

#pragma unroll
        for (int k = 0; k < 16; k++) {
            float4 av0 = *(const float4*)&As[k][ty * 8];
            float4 av1 = *(const float4*)&As[k][ty * 8 + 4];
            float4 bv0 = *(const float4*)&Bs[k][tx * 8];
            float4 bv1 = *(const float4*)&Bs[k][tx * 8 + 4];
            float ar[8] = {av0.x, av0.y, av0.z, av0.w, av1.x, av1.y, av1.z, av1.w};
            float br[8] = {bv0.x, bv0.y, bv0.z, bv0.w, bv1.x, bv1.y, bv1.z, bv1.w};
#pragma unroll
            for (int i = 0; i < 8; i++)
#pragma unroll
                for (int j = 0; j < 8; j++) acc[i][j] += ar[i] * br[j];
        }
    }

#pragma unroll
    for (int i = 0; i < 8; i++) {
        int m = m0 + ty * 8 + i;
        if (HEADOUT) {
            int b = m >> 11;          // m / T
            int t = m & 2047;         // m % T
#pragma unroll
            for (int j = 0; j < 8; j++) {
                int n = n0 + tx * 8 + j;
                int h = n >> 6, d = n & 63;
                O[((size_t)(b * kH + h) * kT + t) * kD + d] = acc[i][j] * alpha;
            }
        } else {
            float* Cp = O + (size_t)m * 1024 + n0 + tx * 8;
#pragma unroll
            for (int j = 0; j < 8; j++) Cp[j] = acc[i][j] * alpha;
        }
    }
}

// All 5 projections in one launch (blockIdx.z selects which)
__global__ void __launch_bounds__(256) proj_gemm(
    const float* __restrict__ noisy, const float* __restrict__ xin,
    const float* __restrict__ Wq1, const float* __restrict__ Wk1,
    const float* __restrict__ Wq2, const float* __restrict__ Wk2,
    const float* __restrict__ Wv) {
    const float* A; const float* W; float* O; float alpha = 1.0f;
    switch (blockIdx.z) {
        case 0: A = noisy; W = Wq1; O = g_q1; alpha = SCALING; break;
        case 1: A = noisy; W = Wk1; O = g_k1; break;
        case 2: A = xin;   W = Wq2; O = g_q2; alpha = SCALING; break;
        case 3: A = xin;   W = Wk2; O = g_k2; break;
        default: A = noisy; W = Wv; O = g_v; break;
    }
    gemm_core<true>(A, W, O, alpha);
}

__global__ void __launch_bounds__(256) out_gemm(const float* __restrict__ Wout,
                                                float* __restrict__ out) {
    gemm_core<false>(g_attn, Wout, out, 1.0f);
}

// ---------------------------------------------------------------------------
// Fused differential attention (flash-style, dual online softmax) + RMSNorm
// Grid: (T/64, B*H). Block: 512 threads (16 warps; warp handles 4 q-rows;
// lane owns columns {lane, lane+32}).
// ---------------------------------------------------------------------------
constexpr int SMEM_FLOATS = 4096 * 2 + 4160 * 2 + 4096 + 4096 * 2; // 28800
constexpr int SMEM_BYTES  = SMEM_FLOATS * 4;                        // 115200

__global__ void __launch_bounds__(512) diffattn(const float* __restrict__ subln_w) {
    extern __shared__ float sm[];
    float* q1s = sm;              // [64][64]
    float* q2s = sm + 4096;       // [64][64]
    float* k1t = sm + 8192;       // [64][65] transposed (d-major)
    float* k2t = k1t + 4160;      // [64][65]
    float* vs  = k2t + 4160;      // [64][64]
    float* p1s = vs + 4096;       // [64][64] warp-private rows
    float* p2s = p1s + 4096;      // [64][64]

    int bh = blockIdx.y, qt = blockIdx.x;
    int tid = threadIdx.x, warp = tid >> 5, lane = tid & 31;
    int r0 = warp * 4;

    const float* Q1g = g_q1 + ((size_t)bh * kT + qt * 64) * kD;
    const float* Q2g = g_q2 + ((size_t)bh * kT + qt * 64) * kD;
    {
        const float4* s1p = (const float4*)Q1g;
        const float4* s2p = (const float4*)Q2g;
        float4* d1 = (float4*)q1s;
        float4* d2 = (float4*)q2s;
        d1[tid] = s1p[tid]; d1[tid + 512] = s1p[tid + 512];
        d2[tid] = s2p[tid]; d2[tid + 512] = s2p[tid + 512];
    }

    float m1[4], l1[4], m2[4], l2[4];
    float acc1[4][2], acc2[4][2];
#pragma unroll
    for (int i = 0; i < 4; i++) {
        m1[i] = -1e30f; m2[i] = -1e30f; l1[i] = 0.0f; l2[i] = 0.0f;
        acc1[i][0] = acc1[i][1] = acc2[i][0] = acc2[i][1] = 0.0f;
    }

    for (int kt = 0; kt < 32; kt++) {
        __syncthreads();   // all warps done with previous K/V tiles
        const float* K1g = g_k1 + ((size_t)bh * kT + kt * 64) * kD;
        const float* K2g = g_k2 + ((size_t)bh * kT + kt * 64) * kD;
        const float* Vg  = g_v  + ((size_t)bh * kT + kt * 64) * kD;
        for (int j = tid; j < 1024; j += 512) {
            int r = j >> 4;
            int dq = (j & 15) << 2;
            float4 kv = *(const float4*)(K1g + r * 64 + dq);
            k1t[(dq + 0) * 65 + r] = kv.x; k1t[(dq + 1) * 65 + r] = kv.y;
            k1t[(dq + 2) * 65 + r] = kv.z; k1t[(dq + 3) * 65 + r] = kv.w;
            kv = *(const float4*)(K2g + r * 64 + dq);
            k2t[(dq + 0) * 65 + r] = kv.x; k2t[(dq + 1) * 65 + r] = kv.y;
            k2t[(dq + 2) * 65 + r] = kv.z; k2t[(dq + 3) * 65 + r] = kv.w;
            *(float4*)(vs + r * 64 + dq) = *(const float4*)(Vg + r * 64 + dq);
        }
        __syncthreads();

        // S = Q K^T for both score sets (Q already carries the 1/sqrt(D) scale)
        float s1[4][2], s2[4][2];
#pragma unroll
        for (int i = 0; i < 4; i++) {
            s1[i][0] = s1[i][1] = 0.0f;
            s2[i][0] = s2[i][1] = 0.0f;
        }
#pragma unroll 4
        for (int d = 0; d < 64; d++) {
            float k1a = k1t[d * 65 + lane], k1b = k1t[d * 65 + lane + 32];
            float k2a = k2t[d * 65 + lane], k2b = k2t[d * 65 + lane + 32];
#pragma unroll
            for (int i = 0; i < 4; i++) {
                float q1v = q1s[(r0 + i) * 64 + d];
                float q2v = q2s[(r0 + i) * 64 + d];
                s1[i][0] += q1v * k1a; s1[i][1] += q1v * k1b;
                s2[i][0] += q2v * k2a; s2[i][1] += q2v * k2b;
            }
        }

        // dual online softmax update; write P tiles (warp-private rows)
#pragma unroll
        for (int i = 0; i < 4; i++) {
            float rm = fmaxf(s1[i][0], s1[i][1]);
#pragma unroll
            for (int o = 16; o; o >>= 1) rm = fmaxf(rm, __shfl_xor_sync(0xffffffffu, rm, o));
            float mn = fmaxf(m1[i], rm);
            float corr = __expf(m1[i] - mn);
            float pa = __expf(s1[i][0] - mn), pb = __expf(s1[i][1] - mn);
            float rs = pa + pb;
#pragma unroll
            for (int o = 16; o; o >>= 1) rs += __shfl_xor_sync(0xffffffffu, rs, o);
            l1[i] = l1[i] * corr + rs;
            acc1[i][0] *= corr; acc1[i][1] *= corr;
            m1[i] = mn;
            p1s[(r0 + i) * 64 + lane] = pa;
            p1s[(r0 + i) * 64 + lane + 32] = pb;

            rm = fmaxf(s2[i][0], s2[i][1]);
#pragma unroll
            for (int o = 16; o; o >>= 1) rm = fmaxf(rm, __shfl_xor_sync(0xffffffffu, rm, o));
            mn = fmaxf(m2[i], rm);
            corr = __expf(m2[i] - mn);
            pa = __expf(s2[i][0] - mn); pb = __expf(s2[i][1] - mn);
            rs = pa + pb;
#pragma unroll
            for (int o = 16; o; o >>= 1) rs += __shfl_xor_sync(0xffffffffu, rs, o);
            l2[i] = l2[i] * corr + rs;
            acc2[i][0] *= corr; acc2[i][1] *= corr;
            m2[i] = mn;
            p2s[(r0 + i) * 64 + lane] = pa;
            p2s[(r0 + i) * 64 + lane + 32] = pb;
        }
        __syncwarp();

        // acc += P @ V  (both score sets)
#pragma unroll 2
        for (int kk = 0; kk < 64; kk++) {
            float va = vs[kk * 64 + lane], vb = vs[kk * 64 + lane + 32];
#pragma unroll
            for (int i = 0; i < 4; i++) {
                float p1v = p1s[(r0 + i) * 64 + kk];
                float p2v = p2s[(r0 + i) * 64 + kk];
                acc1[i][0] += p1v * va; acc1[i][1] += p1v * vb;
                acc2[i][0] += p2v * va; acc2[i][1] += p2v * vb;
            }
        }
        __syncwarp();
    }

    // epilogue: out = a1@V - lam*a2@V, RMSNorm over D, affine, (1-lam_init)
    float lam = g_lambda;
    float wa = subln_w[lane], wb = subln_w[lane + 32];
    int b = bh >> 4, h = bh & 15;
#pragma unroll
    for (int i = 0; i < 4; i++) {
        float oa = acc1[i][0] / l1[i] - lam * (acc2[i][0] / l2[i]);
        float ob = acc1[i][1] / l1[i] - lam * (acc2[i][1] / l2[i]);
        float ss = oa * oa + ob * ob;
#pragma unroll
        for (int o = 16; o; o >>= 1) ss += __shfl_xor_sync(0xffffffffu, ss, o);
        float r = rsqrtf(ss * (1.0f / 64.0f) + EPS);
        float sc = r * (1.0f - LAMBDA_INIT);
        int t = qt * 64 + r0 + i;
        float* dst = g_attn + ((size_t)(b * kT + t) * kH + h) * kD;
        dst[lane]      = oa * sc * wa;
        dst[lane + 32] = ob * sc * wb;
    }
}

// ---------------------------------------------------------------------------
extern "C" void kernel_launch(void* const* d_in, const int* in_sizes, int n_in,
                              void* d_out, int out_size) {
    const float* noisy = (const float*)d_in[0];
    const float* x     = (const float*)d_in[1];
    const float* Wq1   = (const float*)d_in[2];
    const float* Wk1   = (const float*)d_in[3];
    const float* Wq2   = (const float*)d_in[4];
    const float* Wk2   = (const float*)d_in[5];
    const float* Wv    = (const float*)d_in[6];
    const float* Wout  = (const float*)d_in[7];
    const float* lq1   = (const float*)d_in[8];
    const float* lk1   = (const float*)d_in[9];
    const float* lq2   = (const float*)d_in[10];
    const float* lk2   = (const float*)d_in[11];
    const float* subln = (const float*)d_in[12];
    float* out = (float*)d_out;

    cudaFuncSetAttribute(diffattn, cudaFuncAttributeMaxDynamicSharedMemorySize, SMEM_BYTES);

    lambda_kernel<<<1, 32>>>(lq1, lk1, lq2, lk2);
    proj_gemm<<<dim3(8, 32, 5), 256>>>(noisy, x, Wq1, Wk1, Wq2, Wk2, Wv);
    diffattn<<<dim3(32, 32), 512, SMEM_BYTES>>>(subln);
    out_gemm<<<dim3(8, 32), 256>>>(Wout, out);
}

// round 2
// speedup vs baseline: 2.7051x; 2.7051x over previous
#include <cuda_runtime.h>
#include <math.h>
#include <stdint.h>

// Problem constants
constexpr int kB = 2, kT = 2048, kE = 1024, kH = 16, kD = 64;
constexpr float LAMBDA_INIT = 0.47071301834358415f;   // 0.8 - 0.6*exp(-0.6)
constexpr float LOG2E       = 1.4426950408889634f;
constexpr float QSCALE      = 0.125f * LOG2E;         // D^-0.5 folded with log2e
constexpr float EPS         = 1e-5f;

// Scratch (device globals; allocation is forbidden)
__device__ float g_q1[kB * kH * kT * kD];
__device__ float g_k1[kB * kH * kT * kD];
__device__ float g_q2[kB * kH * kT * kD];
__device__ float g_k2[kB * kH * kT * kD];
__device__ float g_v [kB * kH * kT * kD];
__device__ float g_attn[kB * kT * kE];
__device__ float g_lambda;

// ---------------------------------------------------------------------------
// helpers
// ---------------------------------------------------------------------------
__device__ __forceinline__ uint32_t f2tf(float f) {
    uint32_t u;
    asm("cvt.rna.tf32.f32 %0, %1;" : "=r"(u) : "f"(f));
    return u;
}

__device__ __forceinline__ void mma_tf32(float* c, const uint32_t* a, const uint32_t* b) {
    asm volatile(
        "mma.sync.aligned.m16n8k8.row.col.f32.tf32.tf32.f32 "
        "{%0,%1,%2,%3}, {%4,%5,%6,%7}, {%8,%9}, {%0,%1,%2,%3};"
        : "+f"(c[0]), "+f"(c[1]), "+f"(c[2]), "+f"(c[3])
        : "r"(a[0]), "r"(a[1]), "r"(a[2]), "r"(a[3]), "r"(b[0]), "r"(b[1]));
}

// 2^x on the FMA pipe (no MUFU). |x| < ~100 here. ~2.5e-6 rel accuracy.
__device__ __forceinline__ float exp2_fast(float x) {
    float j = x + 12582912.0f;                 // round-to-nearest int in mantissa
    int   e = __float_as_int(j) << 23;         // n << 23 (exponent increment)
    float f = x - (j - 12582912.0f);           // f in [-0.5, 0.5]
    float p =        1.3333558e-3f;            // ln2^5/120
    p = fmaf(p, f,   9.6181291e-3f);           // ln2^4/24
    p = fmaf(p, f,   5.5504109e-2f);           // ln2^3/6
    p = fmaf(p, f,   2.4022651e-1f);           // ln2^2/2
    p = fmaf(p, f,   6.9314718e-1f);           // ln2
    p = fmaf(p, f,   1.0f);
    return __int_as_float(__float_as_int(p) + e);
}

// ---------------------------------------------------------------------------
// lambda = exp(sum lq1*lk1) - exp(sum lq2*lk2) + LAMBDA_INIT
// ---------------------------------------------------------------------------
__global__ void lambda_kernel(const float* __restrict__ lq1, const float* __restrict__ lk1,
                              const float* __restrict__ lq2, const float* __restrict__ lk2) {
    int l = threadIdx.x;
    float a = lq1[l] * lk1[l] + lq1[l + 32] * lk1[l + 32];
    float b = lq2[l] * lk2[l] + lq2[l + 32] * lk2[l + 32];
#pragma unroll
    for (int o = 16; o; o >>= 1) {
        a += __shfl_xor_sync(0xffffffffu, a, o);
        b += __shfl_xor_sync(0xffffffffu, b, o);
    }
    if (l == 0) g_lambda = expf(a) - expf(b) + LAMBDA_INIT;
}

// ---------------------------------------------------------------------------
// tf32 mma GEMM:  C[m,n] = alpha * sum_k A[m,k] * W[n,k]   (M=4096,N=1024,K=1024)
// 128x128 CTA tile, BK=32, 256 threads (8 warps, 2x4 warp grid, 64x32 warp tile).
// smem columns are permuted within each 8-col block: e -> (e&3)*2 + (e>>2), so
// each mma fragment pair (c, c+4) is one LDS.64.
// ---------------------------------------------------------------------------
template <bool HEADOUT>
__device__ __forceinline__ void mma_gemm(const float* __restrict__ A,
                                         const float* __restrict__ W,
                                         float* __restrict__ O, float alpha) {
    __shared__ uint32_t As[128 * 36];
    __shared__ uint32_t Bs[128 * 36];
    const int K = 1024;

    int tid = threadIdx.x, lane = tid & 31, warp = tid >> 5;
    int g = lane >> 2, tg = lane & 3;
    int wm = warp >> 2, wn = warp & 3;
    int m0 = blockIdx.y * 128, n0 = blockIdx.x * 128;

    float acc[4][4][4] = {};

    int lr = tid >> 3;            // 0..31
    int lc = (tid & 7) * 4;       // 0..28
    const float* Ag = A + (size_t)(m0 + lr) * K + lc;
    const float* Wg = W + (size_t)(n0 + lr) * K + lc;
    int pbase = (lc & ~7) + ((lc >> 2) & 1);   // permuted position of element lc

    for (int k0 = 0; k0 < K; k0 += 32) {
        float4 av[4], wv[4];
#pragma unroll
        for (int i = 0; i < 4; i++) {
            av[i] = *(const float4*)(Ag + k0 + (size_t)(i * 32) * K);
            wv[i] = *(const float4*)(Wg + k0 + (size_t)(i * 32) * K);
        }
        __syncthreads();
#pragma unroll
        for (int i = 0; i < 4; i++) {
            uint32_t* pa = As + (lr + 32 * i) * 36 + pbase;
            pa[0] = f2tf(av[i].x); pa[2] = f2tf(av[i].y);
            pa[4] = f2tf(av[i].z); pa[6] = f2tf(av[i].w);
            uint32_t* pb = Bs + (lr + 32 * i) * 36 + pbase;
            pb[0] = f2tf(wv[i].x); pb[2] = f2tf(wv[i].y);
            pb[4] = f2tf(wv[i].z); pb[6] = f2tf(wv[i].w);
        }
        __syncthreads();

#pragma unroll
        for (int k8 = 0; k8 < 4; k8++) {
            uint32_t af[4][4];
#pragma unroll
            for (int mt = 0; mt < 4; mt++) {
                const uint32_t* p = As + (64 * wm + 16 * mt + g) * 36 + 8 * k8 + 2 * tg;
                uint2 lo = *(const uint2*)p;
                uint2 hi = *(const uint2*)(p + 8 * 36);
                af[mt][0] = lo.x; af[mt][1] = hi.x; af[mt][2] = lo.y; af[mt][3] = hi.y;
            }
#pragma unroll
            for (int nt = 0; nt < 4; nt++) {
                uint2 b = *(const uint2*)(Bs + (32 * wn + 8 * nt + g) * 36 + 8 * k8 + 2 * tg);
                uint32_t bf[2] = {b.x, b.y};
#pragma unroll
                for (int mt = 0; mt < 4; mt++) mma_tf32(acc[mt][nt], af[mt], bf);
            }
        }
    }

#pragma unroll
    for (int mt = 0; mt < 4; mt++) {
        int r1 = m0 + 64 * wm + 16 * mt + g;
#pragma unroll
        for (int nt = 0; nt < 4; nt++) {
            int c = n0 + 32 * wn + 8 * nt + 2 * tg;
            float2 v0 = make_float2(acc[mt][nt][0] * alpha, acc[mt][nt][1] * alpha);
            float2 v1 = make_float2(acc[mt][nt][2] * alpha, acc[mt][nt][3] * alpha);
            if (HEADOUT) {
                int b = r1 >> 11, t = r1 & 2047;
                int h = c >> 6, d = c & 63;
                *(float2*)(O + ((size_t)(b * kH + h) * kT + t) * kD + d) = v0;
                *(float2*)(O + ((size_t)(b * kH + h) * kT + t + 8) * kD + d) = v1;
            } else {
                *(float2*)(O + (size_t)r1 * 1024 + c) = v0;
                *(float2*)(O + (size_t)(r1 + 8) * 1024 + c) = v1;
            }
        }
    }
}

__global__ void __launch_bounds__(256) proj_gemm(
    const float* __restrict__ noisy, const float* __restrict__ xin,
    const float* __restrict__ Wq1, const float* __restrict__ Wk1,
    const float* __restrict__ Wq2, const float* __restrict__ Wk2,
    const float* __restrict__ Wv) {
    const float* A; const float* W; float* O; float alpha = 1.0f;
    switch (blockIdx.z) {
        case 0: A = noisy; W = Wq1; O = g_q1; alpha = QSCALE; break;
        case 1: A = noisy; W = Wk1; O = g_k1; break;
        case 2: A = xin;   W = Wq2; O = g_q2; alpha = QSCALE; break;
        case 3: A = xin;   W = Wk2; O = g_k2; break;
        default: A = noisy; W = Wv; O = g_v; break;
    }
    mma_gemm<true>(A, W, O, alpha);
}

__global__ void __launch_bounds__(256) out_gemm(const float* __restrict__ Wout,
                                                float* __restrict__ out) {
    mma_gemm<false>(g_attn, Wout, out, 1.0f);
}

// ---------------------------------------------------------------------------
// Fused differential attention with tf32 mma + FMA-pipe exp2.
// Grid (16 qtiles, 32 bh), 256 threads (8 warps: wm=warp>>1 in 0..3 covers
// 32-row blocks of the 128 q-rows, wn=warp&1 covers 32-key / 32-d halves).
// No softmax max-subtraction (scores bounded), unnormalized accumulation.
// ---------------------------------------------------------------------------
constexpr int AT_SMEM_U32 = 128 * 68 * 2 + 64 * 68 * 2 + 64 * 72 + 128 * 68 * 2; // 48128
constexpr int AT_SMEM_BYTES = AT_SMEM_U32 * 4;  // 192512

__global__ void __launch_bounds__(256, 1) diffattn(const float* __restrict__ subln) {
    extern __shared__ uint32_t smu[];
    uint32_t* q1s = smu;                 // [128][68]
    uint32_t* q2s = q1s + 128 * 68;
    uint32_t* k1s = q2s + 128 * 68;      // [64][68]  (row=key, col=d perm)
    uint32_t* k2s = k1s + 64 * 68;
    uint32_t* vts = k2s + 64 * 68;       // [64][72]  V transposed (row=d, col=key perm)
    uint32_t* p1s = vts + 64 * 72;       // [128][68] (row=q, col=key perm)
    uint32_t* p2s = p1s + 128 * 68;

    int tid = threadIdx.x, lane = tid & 31, warp = tid >> 5;
    int g = lane >> 2, tg = lane & 3;
    int wm = warp >> 1, wn = warp & 1;
    int bh = blockIdx.y, qt = blockIdx.x;

    // ---- load Q1/Q2 tiles (128 x 64) with column-perm + tf32 cvt ----
    const float* Q1g = g_q1 + ((size_t)bh * kT + qt * 128) * kD;
    const float* Q2g = g_q2 + ((size_t)bh * kT + qt * 128) * kD;
#pragma unroll
    for (int it = 0; it < 8; it++) {
        int i = tid + it * 256;          // over 2048 float4
        int row = i >> 4, c4 = i & 15, d0 = c4 * 4;
        int pb = (d0 & ~7) + ((d0 >> 2) & 1);
        float4 a = ((const float4*)Q1g)[i];
        uint32_t* p = q1s + row * 68 + pb;
        p[0] = f2tf(a.x); p[2] = f2tf(a.y); p[4] = f2tf(a.z); p[6] = f2tf(a.w);
        a = ((const float4*)Q2g)[i];
        p = q2s + row * 68 + pb;
        p[0] = f2tf(a.x); p[2] = f2tf(a.y); p[4] = f2tf(a.z); p[6] = f2tf(a.w);
    }

    float acc1[2][4][4] = {}, acc2[2][4][4] = {};
    float l1[4] = {}, l2[4] = {};
    const int pa_off = ((2 * tg) & 3) * 2 + ((2 * tg) >> 2); // perm pos of key 2tg

    const float* K1b = g_k1 + (size_t)bh * kT * kD;
    const float* K2b = g_k2 + (size_t)bh * kT * kD;
    const float* Vb  = g_v  + (size_t)bh * kT * kD;

    for (int kt = 0; kt < 32; kt++) {
        __syncthreads();
        // ---- load K1, K2 (row=key, col=d perm), V transposed (row=d, col=key perm)
        {
            const float4* K1g = (const float4*)(K1b + (size_t)kt * 64 * kD);
            const float4* K2g = (const float4*)(K2b + (size_t)kt * 64 * kD);
            const float4* Vg  = (const float4*)(Vb  + (size_t)kt * 64 * kD);
#pragma unroll
            for (int it = 0; it < 4; it++) {
                int i = tid + it * 256;      // over 1024 float4
                int row = i >> 4, c4 = i & 15, d0 = c4 * 4;
                int pb = (d0 & ~7) + ((d0 >> 2) & 1);
                float4 a = K1g[i];
                uint32_t* p = k1s + row * 68 + pb;
                p[0] = f2tf(a.x); p[2] = f2tf(a.y); p[4] = f2tf(a.z); p[6] = f2tf(a.w);
                a = K2g[i];
                p = k2s + row * 68 + pb;
                p[0] = f2tf(a.x); p[2] = f2tf(a.y); p[4] = f2tf(a.z); p[6] = f2tf(a.w);
                a = Vg[i];
                int pr = (row & ~7) + ((row & 3) << 1) + ((row >> 2) & 1);
                vts[(d0 + 0) * 72 + pr] = f2tf(a.x);
                vts[(d0 + 1) * 72 + pr] = f2tf(a.y);
                vts[(d0 + 2) * 72 + pr] = f2tf(a.z);
                vts[(d0 + 3) * 72 + pr] = f2tf(a.w);
            }
        }
        __syncthreads();

        // ---- S = Q K^T (log2 domain), exp2, P -> smem, l accumulation ----
#pragma unroll
        for (int X = 0; X < 2; X++) {
            const uint32_t* qs = X ? q2s : q1s;
            const uint32_t* ks = X ? k2s : k1s;
            uint32_t* ps = X ? p2s : p1s;
            float* lp = X ? l2 : l1;
            float s[2][4][4] = {};
#pragma unroll
            for (int k8 = 0; k8 < 8; k8++) {
                uint32_t af[2][4];
#pragma unroll
                for (int mt = 0; mt < 2; mt++) {
                    const uint32_t* p = qs + (32 * wm + 16 * mt + g) * 68 + 8 * k8 + 2 * tg;
                    uint2 lo = *(const uint2*)p;
                    uint2 hi = *(const uint2*)(p + 8 * 68);
                    af[mt][0] = lo.x; af[mt][1] = hi.x; af[mt][2] = lo.y; af[mt][3] = hi.y;
                }
#pragma unroll
                for (int nt = 0; nt < 4; nt++) {
                    uint2 b = *(const uint2*)(ks + (32 * wn + 8 * nt + g) * 68 + 8 * k8 + 2 * tg);
                    uint32_t bf[2] = {b.x, b.y};
#pragma unroll
                    for (int mt = 0; mt < 2; mt++) mma_tf32(s[mt][nt], af[mt], bf);
                }
            }
#pragma unroll
            for (int mt = 0; mt < 2; mt++) {
                int row = 32 * wm + 16 * mt + g;
#pragma unroll
                for (int nt = 0; nt < 4; nt++) {
                    int kb = 32 * wn + 8 * nt;
                    float e0 = exp2_fast(s[mt][nt][0]);
                    float e1 = exp2_fast(s[mt][nt][1]);
                    float e2 = exp2_fast(s[mt][nt][2]);
                    float e3 = exp2_fast(s[mt][nt][3]);
                    lp[mt * 2 + 0] += e0 + e1;
                    lp[mt * 2 + 1] += e2 + e3;
                    ps[row * 68 + kb + pa_off]           = f2tf(e0);
                    ps[row * 68 + kb + pa_off + 2]       = f2tf(e1);
                    ps[(row + 8) * 68 + kb + pa_off]     = f2tf(e2);
                    ps[(row + 8) * 68 + kb + pa_off + 2] = f2tf(e3);
                }
            }
        }
        __syncthreads();

        // ---- acc += P @ V (both branches) ----
#pragma unroll
        for (int k8 = 0; k8 < 8; k8++) {
            uint32_t bf[4][2];
#pragma unroll
            for (int nt = 0; nt < 4; nt++) {
                uint2 b = *(const uint2*)(vts + (32 * wn + 8 * nt + g) * 72 + 8 * k8 + 2 * tg);
                bf[nt][0] = b.x; bf[nt][1] = b.y;
            }
#pragma unroll
            for (int X = 0; X < 2; X++) {
                const uint32_t* ps = X ? p2s : p1s;
                float (*ac)[4][4] = X ? acc2 : acc1;
#pragma unroll
                for (int mt = 0; mt < 2; mt++) {
                    const uint32_t* p = ps + (32 * wm + 16 * mt + g) * 68 + 8 * k8 + 2 * tg;
                    uint2 lo = *(const uint2*)p;
                    uint2 hi = *(const uint2*)(p + 8 * 68);
                    uint32_t af[4] = {lo.x, hi.x, lo.y, hi.y};
#pragma unroll
                    for (int nt = 0; nt < 4; nt++) mma_tf32(ac[mt][nt], af, bf[nt]);
                }
            }
        }
    }

    // ---- epilogue: normalize, combine, RMSNorm, affine, write ----
    __syncthreads();   // PV done; p1s reusable as scratch
    float* scr = (float*)p1s;   // [0..256) l1, [256..512) l2, [512..768) ss

#pragma unroll
    for (int i = 0; i < 4; i++) {
        float v1 = l1[i], v2 = l2[i];
        v1 += __shfl_xor_sync(0xffffffffu, v1, 1);
        v1 += __shfl_xor_sync(0xffffffffu, v1, 2);
        v2 += __shfl_xor_sync(0xffffffffu, v2, 1);
        v2 += __shfl_xor_sync(0xffffffffu, v2, 2);
        l1[i] = v1; l2[i] = v2;
    }
    if (tg == 0) {
#pragma unroll
        for (int i = 0; i < 4; i++) {
            int row = 32 * wm + 16 * (i >> 1) + 8 * (i & 1) + g;
            scr[wn * 128 + row] = l1[i];
            scr[256 + wn * 128 + row] = l2[i];
        }
    }
    __syncthreads();

    float inv1[4], inv2[4];
#pragma unroll
    for (int i = 0; i < 4; i++) {
        int row = 32 * wm + 16 * (i >> 1) + 8 * (i & 1) + g;
        inv1[i] = 1.0f / (scr[row] + scr[128 + row]);
        inv2[i] = 1.0f / (scr[256 + row] + scr[384 + row]);
    }
    float lam = g_lambda;
    float ssp[4] = {};
#pragma unroll
    for (int mt = 0; mt < 2; mt++)
#pragma unroll
        for (int nt = 0; nt < 4; nt++)
#pragma unroll
            for (int r = 0; r < 4; r++) {
                int i = mt * 2 + (r >> 1);
                float val = acc1[mt][nt][r] * inv1[i] - lam * (acc2[mt][nt][r] * inv2[i]);
                acc1[mt][nt][r] = val;
                ssp[i] += val * val;
            }
#pragma unroll
    for (int i = 0; i < 4; i++) {
        float v = ssp[i];
        v += __shfl_xor_sync(0xffffffffu, v, 1);
        v += __shfl_xor_sync(0xffffffffu, v, 2);
        ssp[i] = v;
    }
    __syncthreads();
    if (tg == 0) {
#pragma unroll
        for (int i = 0; i < 4; i++) {
            int row = 32 * wm + 16 * (i >> 1) + 8 * (i & 1) + g;
            scr[512 + wn * 128 + row] = ssp[i];
        }
    }
    __syncthreads();
    float scale[4];
#pragma unroll
    for (int i = 0; i < 4; i++) {
        int row = 32 * wm + 16 * (i >> 1) + 8 * (i & 1) + g;
        float SS = scr[512 + row] + scr[640 + row];
        scale[i] = rsqrtf(SS * (1.0f / 64.0f) + EPS) * (1.0f - LAMBDA_INIT);
    }

    int b = bh >> 4, h = bh & 15;
#pragma unroll
    for (int nt = 0; nt < 4; nt++) {
        int d0 = 32 * wn + 8 * nt + 2 * tg;
        float w0 = subln[d0], w1 = subln[d0 + 1];
#pragma unroll
        for (int mt = 0; mt < 2; mt++)
#pragma unroll
            for (int half = 0; half < 2; half++) {
                int i = mt * 2 + half;
                int t = qt * 128 + 32 * wm + 16 * mt + 8 * half + g;
                float2 v = make_float2(acc1[mt][nt][half * 2] * scale[i] * w0,
                                       acc1[mt][nt][half * 2 + 1] * scale[i] * w1);
                *(float2*)(g_attn + ((size_t)(b * kT + t) * kH + h) * kD + d0) = v;
            }
    }
}

// ---------------------------------------------------------------------------
extern "C" void kernel_launch(void* const* d_in, const int* in_sizes, int n_in,
                              void* d_out, int out_size) {
    const float* noisy = (const float*)d_in[0];
    const float* x     = (const float*)d_in[1];
    const float* Wq1   = (const float*)d_in[2];
    const float* Wk1   = (const float*)d_in[3];
    const float* Wq2   = (const float*)d_in[4];
    const float* Wk2   = (const float*)d_in[5];
    const float* Wv    = (const float*)d_in[6];
    const float* Wout  = (const float*)d_in[7];
    const float* lq1   = (const float*)d_in[8];
    const float* lk1   = (const float*)d_in[9];
    const float* lq2   = (const float*)d_in[10];
    const float* lk2   = (const float*)d_in[11];
    const float* subln = (const float*)d_in[12];
    float* out = (float*)d_out;

    cudaFuncSetAttribute(diffattn, cudaFuncAttributeMaxDynamicSharedMemorySize, AT_SMEM_BYTES);

    lambda_kernel<<<1, 32>>>(lq1, lk1, lq2, lk2);
    proj_gemm<<<dim3(8, 32, 5), 256>>>(noisy, x, Wq1, Wk1, Wq2, Wk2, Wv);
    diffattn<<<dim3(16, 32), 256, AT_SMEM_BYTES>>>(subln);
    out_gemm<<<dim3(8, 32), 256>>>(Wout, out);
}

// round 3
// speedup vs baseline: 2.7147x; 1.0035x over previous
#include <cuda_runtime.h>
#include <math.h>
#include <stdint.h>

// Problem constants
constexpr int kB = 2, kT = 2048, kE = 1024, kH = 16, kD = 64;
constexpr float LAMBDA_INIT = 0.47071301834358415f;   // 0.8 - 0.6*exp(-0.6)
constexpr float LOG2E       = 1.4426950408889634f;
constexpr float QSCALE      = 0.125f * LOG2E;         // D^-0.5 folded with log2e
constexpr float EPS         = 1e-5f;

// Scratch (device globals; allocation is forbidden)
__device__ float g_q1[kB * kH * kT * kD];
__device__ float g_k1[kB * kH * kT * kD];
__device__ float g_q2[kB * kH * kT * kD];
__device__ float g_k2[kB * kH * kT * kD];
__device__ float g_v [kB * kH * kT * kD];
__device__ float g_attn[kB * kT * kE];
__device__ float g_lambda;

// ---------------------------------------------------------------------------
// helpers
// ---------------------------------------------------------------------------
__device__ __forceinline__ uint32_t f2tf(float f) {
    uint32_t u;
    asm("cvt.rna.tf32.f32 %0, %1;" : "=r"(u) : "f"(f));
    return u;
}

__device__ __forceinline__ void mma_tf32(float* c, const uint32_t* a, const uint32_t* b) {
    asm volatile(
        "mma.sync.aligned.m16n8k8.row.col.f32.tf32.tf32.f32 "
        "{%0,%1,%2,%3}, {%4,%5,%6,%7}, {%8,%9}, {%0,%1,%2,%3};"
        : "+f"(c[0]), "+f"(c[1]), "+f"(c[2]), "+f"(c[3])
        : "r"(a[0]), "r"(a[1]), "r"(a[2]), "r"(a[3]), "r"(b[0]), "r"(b[1]));
}

// 2^x on the FMA pipe (no MUFU). |x| < ~100 here. ~2.5e-6 rel accuracy.
__device__ __forceinline__ float exp2_fast(float x) {
    float j = x + 12582912.0f;                 // round-to-nearest int in mantissa
    int   e = __float_as_int(j) << 23;         // n << 23 (exponent increment)
    float f = x - (j - 12582912.0f);           // f in [-0.5, 0.5]
    float p =        1.3333558e-3f;            // ln2^5/120
    p = fmaf(p, f,   9.6181291e-3f);           // ln2^4/24
    p = fmaf(p, f,   5.5504109e-2f);           // ln2^3/6
    p = fmaf(p, f,   2.4022651e-1f);           // ln2^2/2
    p = fmaf(p, f,   6.9314718e-1f);           // ln2
    p = fmaf(p, f,   1.0f);
    return __int_as_float(__float_as_int(p) + e);
}

// ---------------------------------------------------------------------------
// lambda = exp(sum lq1*lk1) - exp(sum lq2*lk2) + LAMBDA_INIT
// ---------------------------------------------------------------------------
__global__ void lambda_kernel(const float* __restrict__ lq1, const float* __restrict__ lk1,
                              const float* __restrict__ lq2, const float* __restrict__ lk2) {
    int l = threadIdx.x;
    float a = lq1[l] * lk1[l] + lq1[l + 32] * lk1[l + 32];
    float b = lq2[l] * lk2[l] + lq2[l + 32] * lk2[l + 32];
#pragma unroll
    for (int o = 16; o; o >>= 1) {
        a += __shfl_xor_sync(0xffffffffu, a, o);
        b += __shfl_xor_sync(0xffffffffu, b, o);
    }
    if (l == 0) g_lambda = expf(a) - expf(b) + LAMBDA_INIT;
}

// ---------------------------------------------------------------------------
// tf32 mma GEMM:  C[m,n] = alpha * sum_k A[m,k] * W[n,k]   (M=4096,N=1024,K=1024)
// 128x128 CTA tile, BK=32, 256 threads (8 warps, 2x4 warp grid, 64x32 warp tile).
// smem columns are permuted within each 8-col block: e -> (e&3)*2 + (e>>2), so
// each mma fragment pair (c, c+4) is one LDS.64.
// ---------------------------------------------------------------------------
template <bool HEADOUT>
__device__ __forceinline__ void mma_gemm(const float* __restrict__ A,
                                         const float* __restrict__ W,
                                         float* __restrict__ O, float alpha) {
    __shared__ uint32_t As[128 * 36];
    __shared__ uint32_t Bs[128 * 36];
    const int K = 1024;

    int tid = threadIdx.x, lane = tid & 31, warp = tid >> 5;
    int g = lane >> 2, tg = lane & 3;
    int wm = warp >> 2, wn = warp & 3;
    int m0 = blockIdx.y * 128, n0 = blockIdx.x * 128;

    float acc[4][4][4] = {};

    int lr = tid >> 3;            // 0..31
    int lc = (tid & 7) * 4;       // 0..28
    const float* Ag = A + (size_t)(m0 + lr) * K + lc;
    const float* Wg = W + (size_t)(n0 + lr) * K + lc;
    int pbase = (lc & ~7) + ((lc >> 2) & 1);   // permuted position of element lc

    for (int k0 = 0; k0 < K; k0 += 32) {
        float4 av[4], wv[4];
#pragma unroll
        for (int i = 0; i < 4; i++) {
            av[i] = *(const float4*)(Ag + k0 + (size_t)(i * 32) * K);
            wv[i] = *(const float4*)(Wg + k0 + (size_t)(i * 32) * K);
        }
        __syncthreads();
#pragma unroll
        for (int i = 0; i < 4; i++) {
            uint32_t* pa = As + (lr + 32 * i) * 36 + pbase;
            pa[0] = f2tf(av[i].x); pa[2] = f2tf(av[i].y);
            pa[4] = f2tf(av[i].z); pa[6] = f2tf(av[i].w);
            uint32_t* pb = Bs + (lr + 32 * i) * 36 + pbase;
            pb[0] = f2tf(wv[i].x); pb[2] = f2tf(wv[i].y);
            pb[4] = f2tf(wv[i].z); pb[6] = f2tf(wv[i].w);
        }
        __syncthreads();

#pragma unroll
        for (int k8 = 0; k8 < 4; k8++) {
            uint32_t af[4][4];
#pragma unroll
            for (int mt = 0; mt < 4; mt++) {
                const uint32_t* p = As + (64 * wm + 16 * mt + g) * 36 + 8 * k8 + 2 * tg;
                uint2 lo = *(const uint2*)p;
                uint2 hi = *(const uint2*)(p + 8 * 36);
                af[mt][0] = lo.x; af[mt][1] = hi.x; af[mt][2] = lo.y; af[mt][3] = hi.y;
            }
#pragma unroll
            for (int nt = 0; nt < 4; nt++) {
                uint2 b = *(const uint2*)(Bs + (32 * wn + 8 * nt + g) * 36 + 8 * k8 + 2 * tg);
                uint32_t bf[2] = {b.x, b.y};
#pragma unroll
                for (int mt = 0; mt < 4; mt++) mma_tf32(acc[mt][nt], af[mt], bf);
            }
        }
    }

#pragma unroll
    for (int mt = 0; mt < 4; mt++) {
        int r1 = m0 + 64 * wm + 16 * mt + g;
#pragma unroll
        for (int nt = 0; nt < 4; nt++) {
            int c = n0 + 32 * wn + 8 * nt + 2 * tg;
            float2 v0 = make_float2(acc[mt][nt][0] * alpha, acc[mt][nt][1] * alpha);
            float2 v1 = make_float2(acc[mt][nt][2] * alpha, acc[mt][nt][3] * alpha);
            if (HEADOUT) {
                int b = r1 >> 11, t = r1 & 2047;
                int h = c >> 6, d = c & 63;
                *(float2*)(O + ((size_t)(b * kH + h) * kT + t) * kD + d) = v0;
                *(float2*)(O + ((size_t)(b * kH + h) * kT + t + 8) * kD + d) = v1;
            } else {
                *(float2*)(O + (size_t)r1 * 1024 + c) = v0;
                *(float2*)(O + (size_t)(r1 + 8) * 1024 + c) = v1;
            }
        }
    }
}

__global__ void __launch_bounds__(256) proj_gemm(
    const float* __restrict__ noisy, const float* __restrict__ xin,
    const float* __restrict__ Wq1, const float* __restrict__ Wk1,
    const float* __restrict__ Wq2, const float* __restrict__ Wk2,
    const float* __restrict__ Wv) {
    const float* A; const float* W; float* O; float alpha = 1.0f;
    switch (blockIdx.z) {
        case 0: A = noisy; W = Wq1; O = g_q1; alpha = QSCALE; break;
        case 1: A = noisy; W = Wk1; O = g_k1; break;
        case 2: A = xin;   W = Wq2; O = g_q2; alpha = QSCALE; break;
        case 3: A = xin;   W = Wk2; O = g_k2; break;
        default: A = noisy; W = Wv; O = g_v; break;
    }
    mma_gemm<true>(A, W, O, alpha);
}

__global__ void __launch_bounds__(256) out_gemm(const float* __restrict__ Wout,
                                                float* __restrict__ out) {
    mma_gemm<false>(g_attn, Wout, out, 1.0f);
}

// ---------------------------------------------------------------------------
// Fused differential attention with tf32 mma + FMA-pipe exp2.
// Grid (16 qtiles, 32 bh), 256 threads (8 warps: wm=warp>>1 in 0..3 covers
// 32-row blocks of the 128 q-rows, wn=warp&1 covers 32-key / 32-d halves).
// No softmax max-subtraction (scores bounded), unnormalized accumulation.
// ---------------------------------------------------------------------------
constexpr int AT_SMEM_U32 = 128 * 68 * 2 + 64 * 68 * 2 + 64 * 72 + 128 * 68 * 2; // 48128
constexpr int AT_SMEM_BYTES = AT_SMEM_U32 * 4;  // 192512

__global__ void __launch_bounds__(256, 1) diffattn(const float* __restrict__ subln) {
    extern __shared__ uint32_t smu[];
    uint32_t* q1s = smu;                 // [128][68]
    uint32_t* q2s = q1s + 128 * 68;
    uint32_t* k1s = q2s + 128 * 68;      // [64][68]  (row=key, col=d perm)
    uint32_t* k2s = k1s + 64 * 68;
    uint32_t* vts = k2s + 64 * 68;       // [64][72]  V transposed (row=d, col=key perm)
    uint32_t* p1s = vts + 64 * 72;       // [128][68] (row=q, col=key perm)
    uint32_t* p2s = p1s + 128 * 68;

    int tid = threadIdx.x, lane = tid & 31, warp = tid >> 5;
    int g = lane >> 2, tg = lane & 3;
    int wm = warp >> 1, wn = warp & 1;
    int bh = blockIdx.y, qt = blockIdx.x;

    // ---- load Q1/Q2 tiles (128 x 64) with column-perm + tf32 cvt ----
    const float* Q1g = g_q1 + ((size_t)bh * kT + qt * 128) * kD;
    const float* Q2g = g_q2 + ((size_t)bh * kT + qt * 128) * kD;
#pragma unroll
    for (int it = 0; it < 8; it++) {
        int i = tid + it * 256;          // over 2048 float4
        int row = i >> 4, c4 = i & 15, d0 = c4 * 4;
        int pb = (d0 & ~7) + ((d0 >> 2) & 1);
        float4 a = ((const float4*)Q1g)[i];
        uint32_t* p = q1s + row * 68 + pb;
        p[0] = f2tf(a.x); p[2] = f2tf(a.y); p[4] = f2tf(a.z); p[6] = f2tf(a.w);
        a = ((const float4*)Q2g)[i];
        p = q2s + row * 68 + pb;
        p[0] = f2tf(a.x); p[2] = f2tf(a.y); p[4] = f2tf(a.z); p[6] = f2tf(a.w);
    }

    float acc1[2][4][4] = {}, acc2[2][4][4] = {};
    float l1[4] = {}, l2[4] = {};
    const int pa_off = ((2 * tg) & 3) * 2 + ((2 * tg) >> 2); // perm pos of key 2tg

    const float* K1b = g_k1 + (size_t)bh * kT * kD;
    const float* K2b = g_k2 + (size_t)bh * kT * kD;
    const float* Vb  = g_v  + (size_t)bh * kT * kD;

    for (int kt = 0; kt < 32; kt++) {
        __syncthreads();
        // ---- load K1, K2 (row=key, col=d perm), V transposed (row=d, col=key perm)
        {
            const float4* K1g = (const float4*)(K1b + (size_t)kt * 64 * kD);
            const float4* K2g = (const float4*)(K2b + (size_t)kt * 64 * kD);
            const float4* Vg  = (const float4*)(Vb  + (size_t)kt * 64 * kD);
#pragma unroll
            for (int it = 0; it < 4; it++) {
                int i = tid + it * 256;      // over 1024 float4
                int row = i >> 4, c4 = i & 15, d0 = c4 * 4;
                int pb = (d0 & ~7) + ((d0 >> 2) & 1);
                float4 a = K1g[i];
                uint32_t* p = k1s + row * 68 + pb;
                p[0] = f2tf(a.x); p[2] = f2tf(a.y); p[4] = f2tf(a.z); p[6] = f2tf(a.w);
                a = K2g[i];
                p = k2s + row * 68 + pb;
                p[0] = f2tf(a.x); p[2] = f2tf(a.y); p[4] = f2tf(a.z); p[6] = f2tf(a.w);
                a = Vg[i];
                int pr = (row & ~7) + ((row & 3) << 1) + ((row >> 2) & 1);
                vts[(d0 + 0) * 72 + pr] = f2tf(a.x);
                vts[(d0 + 1) * 72 + pr] = f2tf(a.y);
                vts[(d0 + 2) * 72 + pr] = f2tf(a.z);
                vts[(d0 + 3) * 72 + pr] = f2tf(a.w);
            }
        }
        __syncthreads();

        // ---- S = Q K^T (log2 domain), exp2, P -> smem, l accumulation ----
#pragma unroll
        for (int X = 0; X < 2; X++) {
            const uint32_t* qs = X ? q2s : q1s;
            const uint32_t* ks = X ? k2s : k1s;
            uint32_t* ps = X ? p2s : p1s;
            float* lp = X ? l2 : l1;
            float s[2][4][4] = {};
#pragma unroll
            for (int k8 = 0; k8 < 8; k8++) {
                uint32_t af[2][4];
#pragma unroll
                for (int mt = 0; mt < 2; mt++) {
                    const uint32_t* p = qs + (32 * wm + 16 * mt + g) * 68 + 8 * k8 + 2 * tg;
                    uint2 lo = *(const uint2*)p;
                    uint2 hi = *(const uint2*)(p + 8 * 68);
                    af[mt][0] = lo.x; af[mt][1] = hi.x; af[mt][2] = lo.y; af[mt][3] = hi.y;
                }
#pragma unroll
                for (int nt = 0; nt < 4; nt++) {
                    uint2 b = *(const uint2*)(ks + (32 * wn + 8 * nt + g) * 68 + 8 * k8 + 2 * tg);
                    uint32_t bf[2] = {b.x, b.y};
#pragma unroll
                    for (int mt = 0; mt < 2; mt++) mma_tf32(s[mt][nt], af[mt], bf);
                }
            }
#pragma unroll
            for (int mt = 0; mt < 2; mt++) {
                int row = 32 * wm + 16 * mt + g;
#pragma unroll
                for (int nt = 0; nt < 4; nt++) {
                    int kb = 32 * wn + 8 * nt;
                    float e0 = exp2_fast(s[mt][nt][0]);
                    float e1 = exp2_fast(s[mt][nt][1]);
                    float e2 = exp2_fast(s[mt][nt][2]);
                    float e3 = exp2_fast(s[mt][nt][3]);
                    lp[mt * 2 + 0] += e0 + e1;
                    lp[mt * 2 + 1] += e2 + e3;
                    ps[row * 68 + kb + pa_off]           = f2tf(e0);
                    ps[row * 68 + kb + pa_off + 2]       = f2tf(e1);
                    ps[(row + 8) * 68 + kb + pa_off]     = f2tf(e2);
                    ps[(row + 8) * 68 + kb + pa_off + 2] = f2tf(e3);
                }
            }
        }
        __syncthreads();

        // ---- acc += P @ V (both branches) ----
#pragma unroll
        for (int k8 = 0; k8 < 8; k8++) {
            uint32_t bf[4][2];
#pragma unroll
            for (int nt = 0; nt < 4; nt++) {
                uint2 b = *(const uint2*)(vts + (32 * wn + 8 * nt + g) * 72 + 8 * k8 + 2 * tg);
                bf[nt][0] = b.x; bf[nt][1] = b.y;
            }
#pragma unroll
            for (int X = 0; X < 2; X++) {
                const uint32_t* ps = X ? p2s : p1s;
                float (*ac)[4][4] = X ? acc2 : acc1;
#pragma unroll
                for (int mt = 0; mt < 2; mt++) {
                    const uint32_t* p = ps + (32 * wm + 16 * mt + g) * 68 + 8 * k8 + 2 * tg;
                    uint2 lo = *(const uint2*)p;
                    uint2 hi = *(const uint2*)(p + 8 * 68);
                    uint32_t af[4] = {lo.x, hi.x, lo.y, hi.y};
#pragma unroll
                    for (int nt = 0; nt < 4; nt++) mma_tf32(ac[mt][nt], af, bf[nt]);
                }
            }
        }
    }

    // ---- epilogue: normalize, combine, RMSNorm, affine, write ----
    __syncthreads();   // PV done; p1s reusable as scratch
    float* scr = (float*)p1s;   // [0..256) l1, [256..512) l2, [512..768) ss

#pragma unroll
    for (int i = 0; i < 4; i++) {
        float v1 = l1[i], v2 = l2[i];
        v1 += __shfl_xor_sync(0xffffffffu, v1, 1);
        v1 += __shfl_xor_sync(0xffffffffu, v1, 2);
        v2 += __shfl_xor_sync(0xffffffffu, v2, 1);
        v2 += __shfl_xor_sync(0xffffffffu, v2, 2);
        l1[i] = v1; l2[i] = v2;
    }
    if (tg == 0) {
#pragma unroll
        for (int i = 0; i < 4; i++) {
            int row = 32 * wm + 16 * (i >> 1) + 8 * (i & 1) + g;
            scr[wn * 128 + row] = l1[i];
            scr[256 + wn * 128 + row] = l2[i];
        }
    }
    __syncthreads();

    float inv1[4], inv2[4];
#pragma unroll
    for (int i = 0; i < 4; i++) {
        int row = 32 * wm + 16 * (i >> 1) + 8 * (i & 1) + g;
        inv1[i] = 1.0f / (scr[row] + scr[128 + row]);
        inv2[i] = 1.0f / (scr[256 + row] + scr[384 + row]);
    }
    float lam = g_lambda;
    float ssp[4] = {};
#pragma unroll
    for (int mt = 0; mt < 2; mt++)
#pragma unroll
        for (int nt = 0; nt < 4; nt++)
#pragma unroll
            for (int r = 0; r < 4; r++) {
                int i = mt * 2 + (r >> 1);
                float val = acc1[mt][nt][r] * inv1[i] - lam * (acc2[mt][nt][r] * inv2[i]);
                acc1[mt][nt][r] = val;
                ssp[i] += val * val;
            }
#pragma unroll
    for (int i = 0; i < 4; i++) {
        float v = ssp[i];
        v += __shfl_xor_sync(0xffffffffu, v, 1);
        v += __shfl_xor_sync(0xffffffffu, v, 2);
        ssp[i] = v;
    }
    __syncthreads();
    if (tg == 0) {
#pragma unroll
        for (int i = 0; i < 4; i++) {
            int row = 32 * wm + 16 * (i >> 1) + 8 * (i & 1) + g;
            scr[512 + wn * 128 + row] = ssp[i];
        }
    }
    __syncthreads();
    float scale[4];
#pragma unroll
    for (int i = 0; i < 4; i++) {
        int row = 32 * wm + 16 * (i >> 1) + 8 * (i & 1) + g;
        float SS = scr[512 + row] + scr[640 + row];
        scale[i] = rsqrtf(SS * (1.0f / 64.0f) + EPS) * (1.0f - LAMBDA_INIT);
    }

    int b = bh >> 4, h = bh & 15;
#pragma unroll
    for (int nt = 0; nt < 4; nt++) {
        int d0 = 32 * wn + 8 * nt + 2 * tg;
        float w0 = subln[d0], w1 = subln[d0 + 1];
#pragma unroll
        for (int mt = 0; mt < 2; mt++)
#pragma unroll
            for (int half = 0; half < 2; half++) {
                int i = mt * 2 + half;
                int t = qt * 128 + 32 * wm + 16 * mt + 8 * half + g;
                float2 v = make_float2(acc1[mt][nt][half * 2] * scale[i] * w0,
                                       acc1[mt][nt][half * 2 + 1] * scale[i] * w1);
                *(float2*)(g_attn + ((size_t)(b * kT + t) * kH + h) * kD + d0) = v;
            }
    }
}

// ---------------------------------------------------------------------------
extern "C" void kernel_launch(void* const* d_in, const int* in_sizes, int n_in,
                              void* d_out, int out_size) {
    const float* noisy = (const float*)d_in[0];
    const float* x     = (const float*)d_in[1];
    const float* Wq1   = (const float*)d_in[2];
    const float* Wk1   = (const float*)d_in[3];
    const float* Wq2   = (const float*)d_in[4];
    const float* Wk2   = (const float*)d_in[5];
    const float* Wv    = (const float*)d_in[6];
    const float* Wout  = (const float*)d_in[7];
    const float* lq1   = (const float*)d_in[8];
    const float* lk1   = (const float*)d_in[9];
    const float* lq2   = (const float*)d_in[10];
    const float* lk2   = (const float*)d_in[11];
    const float* subln = (const float*)d_in[12];
    float* out = (float*)d_out;

    cudaFuncSetAttribute(diffattn, cudaFuncAttributeMaxDynamicSharedMemorySize, AT_SMEM_BYTES);

    lambda_kernel<<<1, 32>>>(lq1, lk1, lq2, lk2);
    proj_gemm<<<dim3(8, 32, 5), 256>>>(noisy, x, Wq1, Wk1, Wq2, Wk2, Wv);
    diffattn<<<dim3(16, 32), 256, AT_SMEM_BYTES>>>(subln);
    out_gemm<<<dim3(8, 32), 256>>>(Wout, out);
}

// round 7
// speedup vs baseline: 5.0203x; 1.8493x over previous
#include <cuda_runtime.h>
#include <cuda_fp16.h>
#include <math.h>
#include <stdint.h>

// Problem constants
constexpr int kB = 2, kT = 2048, kE = 1024, kH = 16, kD = 64;
constexpr float LAMBDA_INIT = 0.47071301834358415f;   // 0.8 - 0.6*exp(-0.6)
constexpr float LOG2E       = 1.4426950408889634f;
constexpr float QSCALE      = 0.125f * LOG2E;         // D^-0.5 folded with log2e
constexpr float EPS         = 1e-5f;

// Scratch (device globals; allocation is forbidden). All fp16 now.
__device__ __half g_q1[kB * kH * kT * kD];
__device__ __half g_k1[kB * kH * kT * kD];
__device__ __half g_q2[kB * kH * kT * kD];
__device__ __half g_k2[kB * kH * kT * kD];
__device__ __half g_v [kB * kH * kT * kD];
__device__ __half g_attn[kB * kT * kE];
__device__ float g_lambda;

// ---------------------------------------------------------------------------
// helpers
// ---------------------------------------------------------------------------
__device__ __forceinline__ uint32_t pack_h2(float a, float b) {
    __half2 h = __floats2half2_rn(a, b);   // a -> low, b -> high
    return *reinterpret_cast<uint32_t*>(&h);
}

__device__ __forceinline__ uint32_t prmt(uint32_t a, uint32_t b, uint32_t s) {
    uint32_t r;
    asm("prmt.b32 %0, %1, %2, %3;" : "=r"(r) : "r"(a), "r"(b), "r"(s));
    return r;
}

__device__ __forceinline__ void mma_f16(float* c, const uint32_t* a, const uint32_t* b) {
    asm volatile(
        "mma.sync.aligned.m16n8k16.row.col.f32.f16.f16.f32 "
        "{%0,%1,%2,%3}, {%4,%5,%6,%7}, {%8,%9}, {%0,%1,%2,%3};"
        : "+f"(c[0]), "+f"(c[1]), "+f"(c[2]), "+f"(c[3])
        : "r"(a[0]), "r"(a[1]), "r"(a[2]), "r"(a[3]), "r"(b[0]), "r"(b[1]));
}

// 2^x on the FMA pipe (no MUFU). |x| small here. ~2.5e-6 rel accuracy.
__device__ __forceinline__ float exp2_fast(float x) {
    float j = x + 12582912.0f;
    int   e = __float_as_int(j) << 23;
    float f = x - (j - 12582912.0f);
    float p =        1.3333558e-3f;
    p = fmaf(p, f,   9.6181291e-3f);
    p = fmaf(p, f,   5.5504109e-2f);
    p = fmaf(p, f,   2.4022651e-1f);
    p = fmaf(p, f,   6.9314718e-1f);
    p = fmaf(p, f,   1.0f);
    return __int_as_float(__float_as_int(p) + e);
}

// ---------------------------------------------------------------------------
// lambda = exp(sum lq1*lk1) - exp(sum lq2*lk2) + LAMBDA_INIT
// ---------------------------------------------------------------------------
__global__ void lambda_kernel(const float* __restrict__ lq1, const float* __restrict__ lk1,
                              const float* __restrict__ lq2, const float* __restrict__ lk2) {
    int l = threadIdx.x;
    float a = lq1[l] * lk1[l] + lq1[l + 32] * lk1[l + 32];
    float b = lq2[l] * lk2[l] + lq2[l + 32] * lk2[l + 32];
#pragma unroll
    for (int o = 16; o; o >>= 1) {
        a += __shfl_xor_sync(0xffffffffu, a, o);
        b += __shfl_xor_sync(0xffffffffu, b, o);
    }
    if (l == 0) g_lambda = expf(a) - expf(b) + LAMBDA_INIT;
}

// ---------------------------------------------------------------------------
// fp16 mma GEMM:  C[m,n] = alpha * sum_k A[m,k] * W[n,k]  (M=4096,N=1024,K=1024)
// 128x128 CTA tile, BK=32, 256 threads (8 warps 2x4, 64x32 warp tile),
// m16n8k16 HMMA with fp32 accumulate. smem holds f16x2 (u32) elements; within
// each 8-u32 group, u32 col c is stored at p = (c&3)*2 + (c>>2), so each mma
// fragment pair (tg, tg+4) is a single LDS.64 at offset 2*tg.
// AHALF: A operand already fp16 in gmem (g_attn); else fp32 + cvt on stage.
// ---------------------------------------------------------------------------
template <bool HEADOUT, bool AHALF>
__device__ __forceinline__ void mma_gemm(const void* __restrict__ Ain,
                                         const float* __restrict__ W,
                                         void* __restrict__ Oout, float alpha) {
    __shared__ uint32_t As[128 * 20];
    __shared__ uint32_t Bs[128 * 20];
    const int K = 1024;

    int tid = threadIdx.x, lane = tid & 31, warp = tid >> 5;
    int g = lane >> 2, tg = lane & 3;
    int wm = warp >> 2, wn = warp & 3;
    int m0 = blockIdx.y * 128, n0 = blockIdx.x * 128;

    float acc[4][4][4] = {};

    int lr = tid >> 3;            // 0..31
    int lc = (tid & 7) * 4;       // element col 0..28 (4 elements per thread)
    int c  = lc >> 1;             // u32 col (even)
    int pbase = (c & ~7) + ((c & 3) << 1) + ((c >> 2) & 1);

    const float*  Af = (const float*)Ain;
    const __half* Ah = (const __half*)Ain;

    float4 av[4]; uint2 avh[4]; float4 wv[4];
#pragma unroll
    for (int i = 0; i < 4; i++) {
        if (AHALF) avh[i] = *(const uint2*)(Ah + (size_t)(m0 + lr + 32 * i) * K + lc);
        else       av[i]  = *(const float4*)(Af + (size_t)(m0 + lr + 32 * i) * K + lc);
        wv[i] = *(const float4*)(W + (size_t)(n0 + lr + 32 * i) * K + lc);
    }

    for (int k0 = 0; k0 < K; k0 += 32) {
        __syncthreads();
#pragma unroll
        for (int i = 0; i < 4; i++) {
            uint32_t* pa = As + (lr + 32 * i) * 20 + pbase;
            if (AHALF) { pa[0] = avh[i].x; pa[2] = avh[i].y; }
            else { pa[0] = pack_h2(av[i].x, av[i].y); pa[2] = pack_h2(av[i].z, av[i].w); }
            uint32_t* pb = Bs + (lr + 32 * i) * 20 + pbase;
            pb[0] = pack_h2(wv[i].x, wv[i].y); pb[2] = pack_h2(wv[i].z, wv[i].w);
        }
        __syncthreads();
        if (k0 + 32 < K) {
#pragma unroll
            for (int i = 0; i < 4; i++) {
                if (AHALF) avh[i] = *(const uint2*)(Ah + (size_t)(m0 + lr + 32 * i) * K + k0 + 32 + lc);
                else       av[i]  = *(const float4*)(Af + (size_t)(m0 + lr + 32 * i) * K + k0 + 32 + lc);
                wv[i] = *(const float4*)(W + (size_t)(n0 + lr + 32 * i) * K + k0 + 32 + lc);
            }
        }

#pragma unroll
        for (int k16 = 0; k16 < 2; k16++) {
            uint32_t af[4][4];
#pragma unroll
            for (int mt = 0; mt < 4; mt++) {
                const uint32_t* p = As + (64 * wm + 16 * mt + g) * 20 + k16 * 8 + 2 * tg;
                uint2 lo = *(const uint2*)p;
                uint2 hi = *(const uint2*)(p + 8 * 20);
                af[mt][0] = lo.x; af[mt][1] = hi.x; af[mt][2] = lo.y; af[mt][3] = hi.y;
            }
#pragma unroll
            for (int nt = 0; nt < 4; nt++) {
                uint2 b = *(const uint2*)(Bs + (32 * wn + 8 * nt + g) * 20 + k16 * 8 + 2 * tg);
                uint32_t bf[2] = {b.x, b.y};
#pragma unroll
                for (int mt = 0; mt < 4; mt++) mma_f16(acc[mt][nt], af[mt], bf);
            }
        }
    }

#pragma unroll
    for (int mt = 0; mt < 4; mt++) {
        int r1 = m0 + 64 * wm + 16 * mt + g;
#pragma unroll
        for (int nt = 0; nt < 4; nt++) {
            int cc = n0 + 32 * wn + 8 * nt + 2 * tg;
            float c0 = acc[mt][nt][0] * alpha, c1 = acc[mt][nt][1] * alpha;
            float c2 = acc[mt][nt][2] * alpha, c3 = acc[mt][nt][3] * alpha;
            if (HEADOUT) {
                int b = r1 >> 11, t = r1 & 2047;
                int h = cc >> 6, d = cc & 63;
                __half* base = (__half*)Oout + ((size_t)(b * kH + h) * kT + t) * kD + d;
                *(uint32_t*)base = pack_h2(c0, c1);
                *(uint32_t*)(base + 8 * kD) = pack_h2(c2, c3);
            } else {
                float* O = (float*)Oout;
                *(float2*)(O + (size_t)r1 * 1024 + cc) = make_float2(c0, c1);
                *(float2*)(O + (size_t)(r1 + 8) * 1024 + cc) = make_float2(c2, c3);
            }
        }
    }
}

__global__ void __launch_bounds__(256) proj_gemm(
    const float* __restrict__ noisy, const float* __restrict__ xin,
    const float* __restrict__ Wq1, const float* __restrict__ Wk1,
    const float* __restrict__ Wq2, const float* __restrict__ Wk2,
    const float* __restrict__ Wv) {
    const float* A; const float* W; __half* O; float alpha = 1.0f;
    switch (blockIdx.z) {
        case 0: A = noisy; W = Wq1; O = g_q1; alpha = QSCALE; break;
        case 1: A = noisy; W = Wk1; O = g_k1; break;
        case 2: A = xin;   W = Wq2; O = g_q2; alpha = QSCALE; break;
        case 3: A = xin;   W = Wk2; O = g_k2; break;
        default: A = noisy; W = Wv; O = g_v; break;
    }
    mma_gemm<true, false>(A, W, O, alpha);
}

__global__ void __launch_bounds__(256) out_gemm(const float* __restrict__ Wout,
                                                float* __restrict__ out) {
    mma_gemm<false, true>(g_attn, Wout, out, 1.0f);
}

// ---------------------------------------------------------------------------
// Fused differential attention, all-fp16 operands, fp32 accumulate.
// Grid (16 qtiles of 128 rows, 32 bh), 256 threads. Warp w owns q-rows
// 16w..16w+15 and the full 64-key / 64-d extent -> no cross-warp reductions.
// Q fragments live in registers for the whole CTA (loaded once from gmem).
// P stays in registers: S C-fragments pack directly into PV A-fragments.
// ---------------------------------------------------------------------------
__global__ void __launch_bounds__(256) diffattn(const float* __restrict__ subln) {
    __shared__ uint32_t k1s[64 * 36];   // [key][d-pair perm]
    __shared__ uint32_t k2s[64 * 36];
    __shared__ uint32_t vts[64 * 36];   // [d][key-pair perm] (V transposed)

    int tid = threadIdx.x, lane = tid & 31, warp = tid >> 5;
    int g = lane >> 2, tg = lane & 3;
    int bh = blockIdx.y, qt = blockIdx.x;

    // ---- Q fragments: held in registers across all k-tiles ----
    uint32_t aq1[4][4], aq2[4][4];
    {
        const uint32_t* q1p = (const uint32_t*)(g_q1 + ((size_t)bh * kT + qt * 128 + 16 * warp + g) * kD);
        const uint32_t* q2p = (const uint32_t*)(g_q2 + ((size_t)bh * kT + qt * 128 + 16 * warp + g) * kD);
        const uint32_t* q1p8 = q1p + 8 * 32;   // row g+8
        const uint32_t* q2p8 = q2p + 8 * 32;
#pragma unroll
        for (int k16 = 0; k16 < 4; k16++) {
            aq1[k16][0] = q1p [k16 * 8 + tg];
            aq1[k16][1] = q1p8[k16 * 8 + tg];
            aq1[k16][2] = q1p [k16 * 8 + tg + 4];
            aq1[k16][3] = q1p8[k16 * 8 + tg + 4];
            aq2[k16][0] = q2p [k16 * 8 + tg];
            aq2[k16][1] = q2p8[k16 * 8 + tg];
            aq2[k16][2] = q2p [k16 * 8 + tg + 4];
            aq2[k16][3] = q2p8[k16 * 8 + tg + 4];
        }
    }

    float acc1[8][4] = {}, acc2[8][4] = {};
    float l1a = 0.f, l1b = 0.f, l2a = 0.f, l2b = 0.f;

    const __half* K1b = g_k1 + (size_t)bh * kT * kD;
    const __half* K2b = g_k2 + (size_t)bh * kT * kD;
    const __half* Vb  = g_v  + (size_t)bh * kT * kD;

    // staging registers (prefetched one tile ahead)
    uint4 kr1[2], kr2[2];
    uint32_t vra[4], vrb[4];
    int srow = tid >> 3;                 // 0..31  (K staging: idx = tid + it*256)
    int sc4  = (tid & 7) * 4;            // u32 col
    int sp0  = (sc4 & ~7) + ((sc4 >> 2) & 1);
    int vdp  = tid & 31;                 // V staging: d-pair col
    int vkp2b = tid >> 5;                // key-pair base

    auto ldg_tile = [&](int kt) {
#pragma unroll
        for (int it = 0; it < 2; it++) {
            int row = srow + it * 32;
            kr1[it] = ((const uint4*)(K1b + ((size_t)kt * 64 + row) * kD))[tid & 7];
            kr2[it] = ((const uint4*)(K2b + ((size_t)kt * 64 + row) * kD))[tid & 7];
        }
#pragma unroll
        for (int it = 0; it < 4; it++) {
            int kp2 = vkp2b + it * 8;
            const uint32_t* vp = (const uint32_t*)(Vb + ((size_t)kt * 64 + 2 * kp2) * kD);
            vra[it] = vp[vdp];
            vrb[it] = vp[vdp + 32];
        }
    };

    ldg_tile(0);

    for (int kt = 0; kt < 32; kt++) {
        __syncthreads();
        // ---- store staged tile to smem (perm layouts) ----
#pragma unroll
        for (int it = 0; it < 2; it++) {
            int row = srow + it * 32;
            uint32_t* d1 = k1s + row * 36 + sp0;
            d1[0] = kr1[it].x; d1[2] = kr1[it].y; d1[4] = kr1[it].z; d1[6] = kr1[it].w;
            uint32_t* d2 = k2s + row * 36 + sp0;
            d2[0] = kr2[it].x; d2[2] = kr2[it].y; d2[4] = kr2[it].z; d2[6] = kr2[it].w;
        }
#pragma unroll
        for (int it = 0; it < 4; it++) {
            int kp2 = vkp2b + it * 8;
            int kp = (kp2 & ~7) + ((kp2 & 3) << 1) + ((kp2 >> 2) & 1);
            vts[(2 * vdp) * 36 + kp]     = prmt(vra[it], vrb[it], 0x5410);
            vts[(2 * vdp + 1) * 36 + kp] = prmt(vra[it], vrb[it], 0x7632);
        }
        __syncthreads();
        if (kt < 31) ldg_tile(kt + 1);

        // ---- S = Q K^T (both branches), log2 domain ----
        float s1[8][4] = {}, s2[8][4] = {};
#pragma unroll
        for (int k16 = 0; k16 < 4; k16++) {
#pragma unroll
            for (int nt = 0; nt < 8; nt++) {
                uint2 b1 = *(const uint2*)(k1s + (8 * nt + g) * 36 + k16 * 8 + 2 * tg);
                uint32_t bf1[2] = {b1.x, b1.y};
                mma_f16(s1[nt], aq1[k16], bf1);
                uint2 b2 = *(const uint2*)(k2s + (8 * nt + g) * 36 + k16 * 8 + 2 * tg);
                uint32_t bf2[2] = {b2.x, b2.y};
                mma_f16(s2[nt], aq2[k16], bf2);
            }
        }

        // ---- exp2 + pack P into PV A-fragments (registers only) ----
        uint32_t pu1[8][2], pu2[8][2];
#pragma unroll
        for (int nt = 0; nt < 8; nt++) {
            float e0 = exp2_fast(s1[nt][0]), e1 = exp2_fast(s1[nt][1]);
            float e2 = exp2_fast(s1[nt][2]), e3 = exp2_fast(s1[nt][3]);
            l1a += e0 + e1; l1b += e2 + e3;
            pu1[nt][0] = pack_h2(e0, e1); pu1[nt][1] = pack_h2(e2, e3);
            e0 = exp2_fast(s2[nt][0]); e1 = exp2_fast(s2[nt][1]);
            e2 = exp2_fast(s2[nt][2]); e3 = exp2_fast(s2[nt][3]);
            l2a += e0 + e1; l2b += e2 + e3;
            pu2[nt][0] = pack_h2(e0, e1); pu2[nt][1] = pack_h2(e2, e3);
        }

        // ---- acc += P @ V (both branches) ----
#pragma unroll
        for (int j = 0; j < 4; j++) {
            uint32_t A1[4] = {pu1[2 * j][0], pu1[2 * j][1], pu1[2 * j + 1][0], pu1[2 * j + 1][1]};
            uint32_t A2[4] = {pu2[2 * j][0], pu2[2 * j][1], pu2[2 * j + 1][0], pu2[2 * j + 1][1]};
#pragma unroll
            for (int ntd = 0; ntd < 8; ntd++) {
                uint2 bv = *(const uint2*)(vts + (8 * ntd + g) * 36 + j * 8 + 2 * tg);
                uint32_t bf[2] = {bv.x, bv.y};
                mma_f16(acc1[ntd], A1, bf);
                mma_f16(acc2[ntd], A2, bf);
            }
        }
    }

    // ---- epilogue: normalize, combine, RMSNorm, affine, write fp16 ----
    l1a += __shfl_xor_sync(0xffffffffu, l1a, 1); l1a += __shfl_xor_sync(0xffffffffu, l1a, 2);
    l1b += __shfl_xor_sync(0xffffffffu, l1b, 1); l1b += __shfl_xor_sync(0xffffffffu, l1b, 2);
    l2a += __shfl_xor_sync(0xffffffffu, l2a, 1); l2a += __shfl_xor_sync(0xffffffffu, l2a, 2);
    l2b += __shfl_xor_sync(0xffffffffu, l2b, 1); l2b += __shfl_xor_sync(0xffffffffu, l2b, 2);
    float i1a = 1.0f / l1a, i1b = 1.0f / l1b;
    float i2a = 1.0f / l2a, i2b = 1.0f / l2b;
    float lam = g_lambda;

    float ossa = 0.f, ossb = 0.f;
#pragma unroll
    for (int ntd = 0; ntd < 8; ntd++) {
        float v0 = acc1[ntd][0] * i1a - lam * (acc2[ntd][0] * i2a);
        float v1 = acc1[ntd][1] * i1a - lam * (acc2[ntd][1] * i2a);
        float v2 = acc1[ntd][2] * i1b - lam * (acc2[ntd][2] * i2b);
        float v3 = acc1[ntd][3] * i1b - lam * (acc2[ntd][3] * i2b);
        acc1[ntd][0] = v0; acc1[ntd][1] = v1; acc1[ntd][2] = v2; acc1[ntd][3] = v3;
        ossa += v0 * v0 + v1 * v1;
        ossb += v2 * v2 + v3 * v3;
    }
    ossa += __shfl_xor_sync(0xffffffffu, ossa, 1); ossa += __shfl_xor_sync(0xffffffffu, ossa, 2);
    ossb += __shfl_xor_sync(0xffffffffu, ossb, 1); ossb += __shfl_xor_sync(0xffffffffu, ossb, 2);
    float sca = rsqrtf(ossa * (1.0f / 64.0f) + EPS) * (1.0f - LAMBDA_INIT);
    float scb = rsqrtf(ossb * (1.0f / 64.0f) + EPS) * (1.0f - LAMBDA_INIT);

    int b = bh >> 4, h = bh & 15;
    int t = qt * 128 + 16 * warp + g;
    __half* base = g_attn + ((size_t)(b * kT + t) * kH + h) * kD;
#pragma unroll
    for (int ntd = 0; ntd < 8; ntd++) {
        int d0 = 8 * ntd + 2 * tg;
        float w0 = subln[d0], w1 = subln[d0 + 1];
        *(uint32_t*)(base + d0) = pack_h2(acc1[ntd][0] * sca * w0, acc1[ntd][1] * sca * w1);
        *(uint32_t*)(base + 8 * kH * kD + d0) = pack_h2(acc1[ntd][2] * scb * w0, acc1[ntd][3] * scb * w1);
    }
}

// ---------------------------------------------------------------------------
extern "C" void kernel_launch(void* const* d_in, const int* in_sizes, int n_in,
                              void* d_out, int out_size) {
    const float* noisy = (const float*)d_in[0];
    const float* x     = (const float*)d_in[1];
    const float* Wq1   = (const float*)d_in[2];
    const float* Wk1   = (const float*)d_in[3];
    const float* Wq2   = (const float*)d_in[4];
    const float* Wk2   = (const float*)d_in[5];
    const float* Wv    = (const float*)d_in[6];
    const float* Wout  = (const float*)d_in[7];
    const float* lq1   = (const float*)d_in[8];
    const float* lk1   = (const float*)d_in[9];
    const float* lq2   = (const float*)d_in[10];
    const float* lk2   = (const float*)d_in[11];
    const float* subln = (const float*)d_in[12];
    float* out = (float*)d_out;

    lambda_kernel<<<1, 32>>>(lq1, lk1, lq2, lk2);
    proj_gemm<<<dim3(8, 32, 5), 256>>>(noisy, x, Wq1, Wk1, Wq2, Wk2, Wv);
    diffattn<<<dim3(16, 32), 256>>>(subln);
    out_gemm<<<dim3(8, 32), 256>>>(Wout, out);
}

// round 10
// speedup vs baseline: 8.3092x; 1.6551x over previous
#include <cuda_runtime.h>
#include <cuda_fp16.h>
#include <math.h>
#include <stdint.h>

// Problem constants
constexpr int kB = 2, kT = 2048, kE = 1024, kH = 16, kD = 64;
constexpr float LAMBDA_INIT = 0.47071301834358415f;   // 0.8 - 0.6*exp(-0.6)
constexpr float LOG2E       = 1.4426950408889634f;
constexpr float QSCALE      = 0.125f * LOG2E;         // D^-0.5 folded with log2e
constexpr float EPS         = 1e-5f;

// Scratch (device globals; allocation is forbidden). All fp16.
__device__ __half g_q1[kB * kH * kT * kD];
__device__ __half g_k1[kB * kH * kT * kD];
__device__ __half g_q2[kB * kH * kT * kD];
__device__ __half g_k2[kB * kH * kT * kD];
__device__ __half g_v [kB * kH * kT * kD];
__device__ __half g_attn[kB * kT * kE];
__device__ __half g_nh[kB * kT * kE];     // noisy_y in fp16
__device__ __half g_xh[kB * kT * kE];     // x in fp16
__device__ __half g_wq1[kE * kE], g_wk1[kE * kE], g_wq2[kE * kE];
__device__ __half g_wk2[kE * kE], g_wv[kE * kE], g_wo[kE * kE];
__device__ float g_lambda;

// ---------------------------------------------------------------------------
// helpers
// ---------------------------------------------------------------------------
__device__ __forceinline__ uint32_t pack_h2(float a, float b) {
    __half2 h = __floats2half2_rn(a, b);
    return *reinterpret_cast<uint32_t*>(&h);
}

__device__ __forceinline__ void mma_f16(float* c, const uint32_t* a, const uint32_t* b) {
    asm volatile(
        "mma.sync.aligned.m16n8k16.row.col.f32.f16.f16.f32 "
        "{%0,%1,%2,%3}, {%4,%5,%6,%7}, {%8,%9}, {%0,%1,%2,%3};"
        : "+f"(c[0]), "+f"(c[1]), "+f"(c[2]), "+f"(c[3])
        : "r"(a[0]), "r"(a[1]), "r"(a[2]), "r"(a[3]), "r"(b[0]), "r"(b[1]));
}

__device__ __forceinline__ void ldsm_x4(uint32_t& r0, uint32_t& r1, uint32_t& r2,
                                        uint32_t& r3, uint32_t addr) {
    asm volatile("ldmatrix.sync.aligned.m8n8.x4.shared.b16 {%0,%1,%2,%3}, [%4];"
                 : "=r"(r0), "=r"(r1), "=r"(r2), "=r"(r3) : "r"(addr));
}

__device__ __forceinline__ void ldsm_x4_t(uint32_t& r0, uint32_t& r1, uint32_t& r2,
                                          uint32_t& r3, uint32_t addr) {
    asm volatile("ldmatrix.sync.aligned.m8n8.x4.trans.shared.b16 {%0,%1,%2,%3}, [%4];"
                 : "=r"(r0), "=r"(r1), "=r"(r2), "=r"(r3) : "r"(addr));
}

#define CP_ASYNC16(dst, src) \
    asm volatile("cp.async.cg.shared.global [%0], [%1], 16;" :: "r"(dst), "l"(src))
#define CP_COMMIT() asm volatile("cp.async.commit_group;")

// 2^x on the FMA pipe (no MUFU). ~2.5e-6 rel accuracy.
__device__ __forceinline__ float exp2_fast(float x) {
    float j = x + 12582912.0f;
    int   e = __float_as_int(j) << 23;
    float f = x - (j - 12582912.0f);
    float p =        1.3333558e-3f;
    p = fmaf(p, f,   9.6181291e-3f);
    p = fmaf(p, f,   5.5504109e-2f);
    p = fmaf(p, f,   2.4022651e-1f);
    p = fmaf(p, f,   6.9314718e-1f);
    p = fmaf(p, f,   1.0f);
    return __int_as_float(__float_as_int(p) + e);
}

// ---------------------------------------------------------------------------
// fp32 -> fp16 convert (vectorized), optional scale
// ---------------------------------------------------------------------------
__global__ void __launch_bounds__(256) cvt_h(const float* __restrict__ src,
                                             __half* __restrict__ dst,
                                             int n4, float alpha) {
    int i = blockIdx.x * 256 + threadIdx.x;
    if (i < n4) {
        float4 v = ((const float4*)src)[i];
        uint2 o;
        o.x = pack_h2(v.x * alpha, v.y * alpha);
        o.y = pack_h2(v.z * alpha, v.w * alpha);
        ((uint2*)dst)[i] = o;
    }
}

// ---------------------------------------------------------------------------
// lambda = exp(sum lq1*lk1) - exp(sum lq2*lk2) + LAMBDA_INIT
// ---------------------------------------------------------------------------
__global__ void lambda_kernel(const float* __restrict__ lq1, const float* __restrict__ lk1,
                              const float* __restrict__ lq2, const float* __restrict__ lk2) {
    int l = threadIdx.x;
    float a = lq1[l] * lk1[l] + lq1[l + 32] * lk1[l + 32];
    float b = lq2[l] * lk2[l] + lq2[l + 32] * lk2[l + 32];
#pragma unroll
    for (int o = 16; o; o >>= 1) {
        a += __shfl_xor_sync(0xffffffffu, a, o);
        b += __shfl_xor_sync(0xffffffffu, b, o);
    }
    if (l == 0) g_lambda = expf(a) - expf(b) + LAMBDA_INIT;
}

// ---------------------------------------------------------------------------
// fp16 GEMM with cp.async double-buffer + ldmatrix + m16n8k16 HMMA (fp32 acc).
// C[m,n] = sum_k A[m,k] * W[n,k]; M=4096, N=1024, K=1024.
// 128x128 CTA tile, BK=64, 256 threads (8 warps 2x4, 64x32 warp tiles).
// smem layout: rows of 64 f16 (128B); 16B chunk c of row r stored at c^(r&7).
// ---------------------------------------------------------------------------
template <bool HEADOUT>
__device__ __forceinline__ void mma_gemm_h(const __half* __restrict__ A,
                                           const __half* __restrict__ Wh,
                                           void* __restrict__ Oout) {
    extern __shared__ __align__(16) char dyn[];
    const int K = 1024;
    const uint32_t aS = (uint32_t)__cvta_generic_to_shared(dyn);
    const uint32_t bS = aS + 32768;       // 2 stages x 128x64 f16 = 32768 B

    int tid = threadIdx.x, lane = tid & 31, warp = tid >> 5;
    int g = lane >> 2, tg = lane & 3;
    int wm = warp >> 2, wn = warp & 3;
    int m0 = blockIdx.y * 128, n0 = blockIdx.x * 128;
    int sw = lane & 7;

    // fragment addressing (rows offset by multiples of 8 keep row&7 == lane&7)
    int arow = (lane & 7) + (((lane >> 3) & 1) << 3);   // A: M0 lo/klo, M1 hi/klo, M2 lo/khi, M3 hi/khi
    int ahi  = (lane >> 4) & 1;
    int brow = (lane & 7) + (((lane >> 4) & 1) << 3);   // B: M0 nlo/klo, M1 nlo/khi, M2 nhi/klo, M3 nhi/khi
    int bhi  = (lane >> 3) & 1;

    auto stage = [&](int k0, int buf) {
        uint32_t ab = aS + buf * 16384;
        uint32_t bb = bS + buf * 16384;
#pragma unroll
        for (int it = 0; it < 4; it++) {
            int ch = tid + it * 256;               // 1024 chunks per tile
            int r = ch >> 3, c = ch & 7;
            uint32_t so = r * 128 + ((c ^ (r & 7)) << 4);
            CP_ASYNC16(ab + so, A + (size_t)(m0 + r) * K + k0 + c * 8);
            CP_ASYNC16(bb + so, Wh + (size_t)(n0 + r) * K + k0 + c * 8);
        }
    };

    float acc[4][4][4] = {};

    stage(0, 0);
    CP_COMMIT();

    for (int i = 0; i < 16; i++) {
        if (i < 15) {
            stage((i + 1) * 64, (i + 1) & 1);
            CP_COMMIT();
            asm volatile("cp.async.wait_group 1;");
        } else {
            asm volatile("cp.async.wait_group 0;");
        }
        __syncthreads();
        uint32_t ab = aS + (i & 1) * 16384;
        uint32_t bb = bS + (i & 1) * 16384;

#pragma unroll
        for (int kc = 0; kc < 4; kc++) {
            uint32_t af[4][4];
#pragma unroll
            for (int mt = 0; mt < 4; mt++) {
                uint32_t ad = ab + (64 * wm + 16 * mt + arow) * 128 +
                              (((2 * kc + ahi) ^ sw) << 4);
                ldsm_x4(af[mt][0], af[mt][1], af[mt][2], af[mt][3], ad);
            }
#pragma unroll
            for (int p = 0; p < 2; p++) {
                uint32_t bd = bb + (32 * wn + 16 * p + brow) * 128 +
                              (((2 * kc + bhi) ^ sw) << 4);
                uint32_t b0, b1, b2, b3;
                ldsm_x4(b0, b1, b2, b3, bd);
                uint32_t bfa[2] = {b0, b1}, bfb[2] = {b2, b3};
#pragma unroll
                for (int mt = 0; mt < 4; mt++) {
                    mma_f16(acc[mt][2 * p], af[mt], bfa);
                    mma_f16(acc[mt][2 * p + 1], af[mt], bfb);
                }
            }
        }
        __syncthreads();
    }

#pragma unroll
    for (int mt = 0; mt < 4; mt++) {
        int r1 = m0 + 64 * wm + 16 * mt + g;
#pragma unroll
        for (int nt = 0; nt < 4; nt++) {
            int cc = n0 + 32 * wn + 8 * nt + 2 * tg;
            float c0 = acc[mt][nt][0], c1 = acc[mt][nt][1];
            float c2 = acc[mt][nt][2], c3 = acc[mt][nt][3];
            if (HEADOUT) {
                int b = r1 >> 11, t = r1 & 2047;
                int h = cc >> 6, d = cc & 63;
                __half* base = (__half*)Oout + ((size_t)(b * kH + h) * kT + t) * kD + d;
                *(uint32_t*)base = pack_h2(c0, c1);
                *(uint32_t*)(base + 8 * kD) = pack_h2(c2, c3);
            } else {
                float* O = (float*)Oout;
                *(float2*)(O + (size_t)r1 * 1024 + cc) = make_float2(c0, c1);
                *(float2*)(O + (size_t)(r1 + 8) * 1024 + cc) = make_float2(c2, c3);
            }
        }
    }
}

__global__ void __launch_bounds__(256) proj_gemm() {
    const __half* A; const __half* W; __half* O;
    switch (blockIdx.z) {
        case 0: A = g_nh; W = g_wq1; O = g_q1; break;   // QSCALE folded into g_wq1
        case 1: A = g_nh; W = g_wk1; O = g_k1; break;
        case 2: A = g_xh; W = g_wq2; O = g_q2; break;   // QSCALE folded into g_wq2
        case 3: A = g_xh; W = g_wk2; O = g_k2; break;
        default: A = g_nh; W = g_wv; O = g_v; break;
    }
    mma_gemm_h<true>(A, W, O);
}

__global__ void __launch_bounds__(256) out_gemm(float* __restrict__ out) {
    mma_gemm_h<false>(g_attn, g_wo, out);
}

// ---------------------------------------------------------------------------
// Fused differential attention: cp.async double-buffered K1/K2/V tiles,
// ldmatrix fragment loads (V via ldmatrix.trans), register-resident Q and P,
// FMA-pipe exp2, fused RMSNorm epilogue.
// Grid (16 qtiles of 128 rows, 32 bh), 256 threads; warp w owns q-rows
// 16w..16w+15 and the full 64-key / 64-d extent.
// ---------------------------------------------------------------------------
constexpr int AT_SMEM = 3 * 2 * 64 * 64 * 2;   // 49152 bytes

__global__ void __launch_bounds__(256) diffattn(const float* __restrict__ subln) {
    extern __shared__ __align__(16) char dyn[];
    const uint32_t k1S = (uint32_t)__cvta_generic_to_shared(dyn);
    const uint32_t k2S = k1S + 16384;
    const uint32_t vS  = k1S + 32768;

    int tid = threadIdx.x, lane = tid & 31, warp = tid >> 5;
    int g = lane >> 2, tg = lane & 3;
    int bh = blockIdx.y, qt = blockIdx.x;
    int sw = lane & 7;

    int brow = (lane & 7) + (((lane >> 4) & 1) << 3);   // K (B operand, non-trans)
    int bhi  = (lane >> 3) & 1;
    int vrow = (lane & 7) + (((lane >> 3) & 1) << 3);   // V (B operand, trans)
    int vhi  = (lane >> 4) & 1;

    // ---- Q fragments: registers for the whole CTA ----
    uint32_t aq1[4][4], aq2[4][4];
    {
        const uint32_t* q1p = (const uint32_t*)(g_q1 + ((size_t)bh * kT + qt * 128 + 16 * warp + g) * kD);
        const uint32_t* q2p = (const uint32_t*)(g_q2 + ((size_t)bh * kT + qt * 128 + 16 * warp + g) * kD);
        const uint32_t* q1p8 = q1p + 8 * 32;
        const uint32_t* q2p8 = q2p + 8 * 32;
#pragma unroll
        for (int k16 = 0; k16 < 4; k16++) {
            aq1[k16][0] = q1p [k16 * 8 + tg];
            aq1[k16][1] = q1p8[k16 * 8 + tg];
            aq1[k16][2] = q1p [k16 * 8 + tg + 4];
            aq1[k16][3] = q1p8[k16 * 8 + tg + 4];
            aq2[k16][0] = q2p [k16 * 8 + tg];
            aq2[k16][1] = q2p8[k16 * 8 + tg];
            aq2[k16][2] = q2p [k16 * 8 + tg + 4];
            aq2[k16][3] = q2p8[k16 * 8 + tg + 4];
        }
    }

    const __half* K1b = g_k1 + (size_t)bh * kT * kD;
    const __half* K2b = g_k2 + (size_t)bh * kT * kD;
    const __half* Vb  = g_v  + (size_t)bh * kT * kD;

    auto stage = [&](int kt, int buf) {
        uint32_t o = buf * 8192;
#pragma unroll
        for (int it = 0; it < 2; it++) {
            int ch = tid + it * 256;               // 512 chunks per tile
            int r = ch >> 3, c = ch & 7;
            uint32_t so = o + r * 128 + ((c ^ (r & 7)) << 4);
            const __half* rowp = K1b + ((size_t)kt * 64 + r) * kD + c * 8;
            CP_ASYNC16(k1S + so, rowp);
            CP_ASYNC16(k2S + so, K2b + ((size_t)kt * 64 + r) * kD + c * 8);
            CP_ASYNC16(vS + so,  Vb  + ((size_t)kt * 64 + r) * kD + c * 8);
        }
    };

    float acc1[8][4] = {}, acc2[8][4] = {};
    float l1a = 0.f, l1b = 0.f, l2a = 0.f, l2b = 0.f;

    stage(0, 0);
    CP_COMMIT();

    for (int kt = 0; kt < 32; kt++) {
        if (kt < 31) {
            stage(kt + 1, (kt + 1) & 1);
            CP_COMMIT();
            asm volatile("cp.async.wait_group 1;");
        } else {
            asm volatile("cp.async.wait_group 0;");
        }
        __syncthreads();
        uint32_t o = (kt & 1) * 8192;
        uint32_t k1b = k1S + o, k2b = k2S + o, vb = vS + o;

        // ---- S = Q K^T (both branches), log2 domain ----
        float s1[8][4] = {}, s2[8][4] = {};
#pragma unroll
        for (int kc = 0; kc < 4; kc++) {
            uint32_t csel = ((2 * kc + bhi) ^ sw) << 4;
#pragma unroll
            for (int p = 0; p < 4; p++) {
                uint32_t roff = (16 * p + brow) * 128 + csel;
                uint32_t b0, b1, b2, b3;
                ldsm_x4(b0, b1, b2, b3, k1b + roff);
                uint32_t bfa[2] = {b0, b1}, bfb[2] = {b2, b3};
                mma_f16(s1[2 * p], aq1[kc], bfa);
                mma_f16(s1[2 * p + 1], aq1[kc], bfb);
                ldsm_x4(b0, b1, b2, b3, k2b + roff);
                uint32_t bfc[2] = {b0, b1}, bfd[2] = {b2, b3};
                mma_f16(s2[2 * p], aq2[kc], bfc);
                mma_f16(s2[2 * p + 1], aq2[kc], bfd);
            }
        }

        // ---- exp2 + pack P into PV A-fragments (registers only) ----
        uint32_t pu1[8][2], pu2[8][2];
#pragma unroll
        for (int nt = 0; nt < 8; nt++) {
            float e0 = exp2_fast(s1[nt][0]), e1 = exp2_fast(s1[nt][1]);
            float e2 = exp2_fast(s1[nt][2]), e3 = exp2_fast(s1[nt][3]);
            l1a += e0 + e1; l1b += e2 + e3;
            pu1[nt][0] = pack_h2(e0, e1); pu1[nt][1] = pack_h2(e2, e3);
            e0 = exp2_fast(s2[nt][0]); e1 = exp2_fast(s2[nt][1]);
            e2 = exp2_fast(s2[nt][2]); e3 = exp2_fast(s2[nt][3]);
            l2a += e0 + e1; l2b += e2 + e3;
            pu2[nt][0] = pack_h2(e0, e1); pu2[nt][1] = pack_h2(e2, e3);
        }

        // ---- acc += P @ V (both branches), V via ldmatrix.trans ----
#pragma unroll
        for (int j = 0; j < 4; j++) {
            uint32_t A1[4] = {pu1[2 * j][0], pu1[2 * j][1], pu1[2 * j + 1][0], pu1[2 * j + 1][1]};
            uint32_t A2[4] = {pu2[2 * j][0], pu2[2 * j][1], pu2[2 * j + 1][0], pu2[2 * j + 1][1]};
            uint32_t rbase = vb + (16 * j + vrow) * 128;
#pragma unroll
            for (int p = 0; p < 4; p++) {
                uint32_t b0, b1, b2, b3;
                ldsm_x4_t(b0, b1, b2, b3, rbase + (((2 * p + vhi) ^ sw) << 4));
                uint32_t bfa[2] = {b0, b1}, bfb[2] = {b2, b3};
                mma_f16(acc1[2 * p], A1, bfa);
                mma_f16(acc1[2 * p + 1], A1, bfb);
                mma_f16(acc2[2 * p], A2, bfa);
                mma_f16(acc2[2 * p + 1], A2, bfb);
            }
        }
        __syncthreads();
    }

    // ---- epilogue: normalize, combine, RMSNorm, affine, write fp16 ----
    l1a += __shfl_xor_sync(0xffffffffu, l1a, 1); l1a += __shfl_xor_sync(0xffffffffu, l1a, 2);
    l1b += __shfl_xor_sync(0xffffffffu, l1b, 1); l1b += __shfl_xor_sync(0xffffffffu, l1b, 2);
    l2a += __shfl_xor_sync(0xffffffffu, l2a, 1); l2a += __shfl_xor_sync(0xffffffffu, l2a, 2);
    l2b += __shfl_xor_sync(0xffffffffu, l2b, 1); l2b += __shfl_xor_sync(0xffffffffu, l2b, 2);
    float i1a = 1.0f / l1a, i1b = 1.0f / l1b;
    float i2a = 1.0f / l2a, i2b = 1.0f / l2b;
    float lam = g_lambda;

    float ossa = 0.f, ossb = 0.f;
#pragma unroll
    for (int ntd = 0; ntd < 8; ntd++) {
        float v0 = acc1[ntd][0] * i1a - lam * (acc2[ntd][0] * i2a);
        float v1 = acc1[ntd][1] * i1a - lam * (acc2[ntd][1] * i2a);
        float v2 = acc1[ntd][2] * i1b - lam * (acc2[ntd][2] * i2b);
        float v3 = acc1[ntd][3] * i1b - lam * (acc2[ntd][3] * i2b);
        acc1[ntd][0] = v0; acc1[ntd][1] = v1; acc1[ntd][2] = v2; acc1[ntd][3] = v3;
        ossa += v0 * v0 + v1 * v1;
        ossb += v2 * v2 + v3 * v3;
    }
    ossa += __shfl_xor_sync(0xffffffffu, ossa, 1); ossa += __shfl_xor_sync(0xffffffffu, ossa, 2);
    ossb += __shfl_xor_sync(0xffffffffu, ossb, 1); ossb += __shfl_xor_sync(0xffffffffu, ossb, 2);
    float sca = rsqrtf(ossa * (1.0f / 64.0f) + EPS) * (1.0f - LAMBDA_INIT);
    float scb = rsqrtf(ossb * (1.0f / 64.0f) + EPS) * (1.0f - LAMBDA_INIT);

    int b = bh >> 4, h = bh & 15;
    int t = qt * 128 + 16 * warp + g;
    __half* base = g_attn + ((size_t)(b * kT + t) * kH + h) * kD;
#pragma unroll
    for (int ntd = 0; ntd < 8; ntd++) {
        int d0 = 8 * ntd + 2 * tg;
        float w0 = subln[d0], w1 = subln[d0 + 1];
        *(uint32_t*)(base + d0) = pack_h2(acc1[ntd][0] * sca * w0, acc1[ntd][1] * sca * w1);
        *(uint32_t*)(base + 8 * kH * kD + d0) = pack_h2(acc1[ntd][2] * scb * w0, acc1[ntd][3] * scb * w1);
    }
}

// ---------------------------------------------------------------------------
extern "C" void kernel_launch(void* const* d_in, const int* in_sizes, int n_in,
                              void* d_out, int out_size) {
    const float* noisy = (const float*)d_in[0];
    const float* x     = (const float*)d_in[1];
    const float* Wq1   = (const float*)d_in[2];
    const float* Wk1   = (const float*)d_in[3];
    const float* Wq2   = (const float*)d_in[4];
    const float* Wk2   = (const float*)d_in[5];
    const float* Wv    = (const float*)d_in[6];
    const float* Wout  = (const float*)d_in[7];
    const float* lq1   = (const float*)d_in[8];
    const float* lk1   = (const float*)d_in[9];
    const float* lq2   = (const float*)d_in[10];
    const float* lk2   = (const float*)d_in[11];
    const float* subln = (const float*)d_in[12];
    float* out = (float*)d_out;

    static bool attr_done = false;
    if (!attr_done) {
        cudaFuncSetAttribute(proj_gemm, cudaFuncAttributeMaxDynamicSharedMemorySize, 65536);
        cudaFuncSetAttribute(out_gemm, cudaFuncAttributeMaxDynamicSharedMemorySize, 65536);
        cudaFuncSetAttribute(diffattn, cudaFuncAttributeMaxDynamicSharedMemorySize, AT_SMEM);
        attr_done = true;
    }

    __half *nh, *xh, *wq1, *wk1, *wq2, *wk2, *wv, *wo;
    cudaGetSymbolAddress((void**)&nh, g_nh);
    cudaGetSymbolAddress((void**)&xh, g_xh);
    cudaGetSymbolAddress((void**)&wq1, g_wq1);
    cudaGetSymbolAddress((void**)&wk1, g_wk1);
    cudaGetSymbolAddress((void**)&wq2, g_wq2);
    cudaGetSymbolAddress((void**)&wk2, g_wk2);
    cudaGetSymbolAddress((void**)&wv, g_wv);
    cudaGetSymbolAddress((void**)&wo, g_wo);

    // fp32 -> fp16 converts (QSCALE folded into Wq1/Wq2)
    cvt_h<<<4096, 256>>>(noisy, nh, kB * kT * kE / 4, 1.0f);
    cvt_h<<<4096, 256>>>(x, xh, kB * kT * kE / 4, 1.0f);
    cvt_h<<<1024, 256>>>(Wq1, wq1, kE * kE / 4, QSCALE);
    cvt_h<<<1024, 256>>>(Wk1, wk1, kE * kE / 4, 1.0f);
    cvt_h<<<1024, 256>>>(Wq2, wq2, kE * kE / 4, QSCALE);
    cvt_h<<<1024, 256>>>(Wk2, wk2, kE * kE / 4, 1.0f);
    cvt_h<<<1024, 256>>>(Wv, wv, kE * kE / 4, 1.0f);
    cvt_h<<<1024, 256>>>(Wout, wo, kE * kE / 4, 1.0f);

    lambda_kernel<<<1, 32>>>(lq1, lk1, lq2, lk2);
    proj_gemm<<<dim3(8, 32, 5), 256, 65536>>>();
    diffattn<<<dim3(16, 32), 256, AT_SMEM>>>(subln);
    out_gemm<<<dim3(8, 32), 256, 65536>>>(out);
}

// round 12
// speedup vs baseline: 9.9951x; 1.2029x over previous
#include <cuda_runtime.h>
#include <cuda_fp16.h>
#include <math.h>
#include <stdint.h>

// Problem constants
constexpr int kB = 2, kT = 2048, kE = 1024, kH = 16, kD = 64;
constexpr float LAMBDA_INIT = 0.47071301834358415f;   // 0.8 - 0.6*exp(-0.6)
constexpr float LOG2E       = 1.4426950408889634f;
constexpr float QSCALE      = 0.125f * LOG2E;         // D^-0.5 folded with log2e
constexpr float EPS         = 1e-5f;

// Scratch (device globals; allocation is forbidden). All fp16.
__device__ __half g_q1[kB * kH * kT * kD];
__device__ __half g_k1[kB * kH * kT * kD];
__device__ __half g_q2[kB * kH * kT * kD];
__device__ __half g_k2[kB * kH * kT * kD];
__device__ __half g_v [kB * kH * kT * kD];
__device__ __half g_attn[kB * kT * kE];
__device__ __half g_nh[kB * kT * kE];
__device__ __half g_xh[kB * kT * kE];
__device__ __half g_wq1[kE * kE], g_wk1[kE * kE], g_wq2[kE * kE];
__device__ __half g_wk2[kE * kE], g_wv[kE * kE], g_wo[kE * kE];
__device__ float g_lambda;

// ---------------------------------------------------------------------------
// helpers
// ---------------------------------------------------------------------------
__device__ __forceinline__ uint32_t pack_h2(float a, float b) {
    __half2 h = __floats2half2_rn(a, b);
    return *reinterpret_cast<uint32_t*>(&h);
}

__device__ __forceinline__ float ex2f(float x) {
    float r;
    asm("ex2.approx.ftz.f32 %0, %1;" : "=f"(r) : "f"(x));
    return r;
}

__device__ __forceinline__ void mma_f16(float* c, const uint32_t* a, const uint32_t* b) {
    asm volatile(
        "mma.sync.aligned.m16n8k16.row.col.f32.f16.f16.f32 "
        "{%0,%1,%2,%3}, {%4,%5,%6,%7}, {%8,%9}, {%0,%1,%2,%3};"
        : "+f"(c[0]), "+f"(c[1]), "+f"(c[2]), "+f"(c[3])
        : "r"(a[0]), "r"(a[1]), "r"(a[2]), "r"(a[3]), "r"(b[0]), "r"(b[1]));
}

__device__ __forceinline__ void ldsm_x4(uint32_t& r0, uint32_t& r1, uint32_t& r2,
                                        uint32_t& r3, uint32_t addr) {
    asm volatile("ldmatrix.sync.aligned.m8n8.x4.shared.b16 {%0,%1,%2,%3}, [%4];"
                 : "=r"(r0), "=r"(r1), "=r"(r2), "=r"(r3) : "r"(addr));
}

__device__ __forceinline__ void ldsm_x4_t(uint32_t& r0, uint32_t& r1, uint32_t& r2,
                                          uint32_t& r3, uint32_t addr) {
    asm volatile("ldmatrix.sync.aligned.m8n8.x4.trans.shared.b16 {%0,%1,%2,%3}, [%4];"
                 : "=r"(r0), "=r"(r1), "=r"(r2), "=r"(r3) : "r"(addr));
}

#define CP_ASYNC16(dst, src) \
    asm volatile("cp.async.cg.shared.global [%0], [%1], 16;" :: "r"(dst), "l"(src))
#define CP_COMMIT() asm volatile("cp.async.commit_group;")

// ---------------------------------------------------------------------------
// fp32 -> fp16 converts, fused
// ---------------------------------------------------------------------------
__global__ void __launch_bounds__(256) cvt_weights(
    const float* __restrict__ Wq1, const float* __restrict__ Wk1,
    const float* __restrict__ Wq2, const float* __restrict__ Wk2,
    const float* __restrict__ Wv, const float* __restrict__ Wo) {
    const float* src; __half* dst; float alpha = 1.0f;
    switch (blockIdx.y) {
        case 0: src = Wq1; dst = g_wq1; alpha = QSCALE; break;
        case 1: src = Wk1; dst = g_wk1; break;
        case 2: src = Wq2; dst = g_wq2; alpha = QSCALE; break;
        case 3: src = Wk2; dst = g_wk2; break;
        case 4: src = Wv;  dst = g_wv;  break;
        default: src = Wo; dst = g_wo;  break;
    }
    int i = blockIdx.x * 256 + threadIdx.x;          // kE*kE/4 float4
    float4 v = ((const float4*)src)[i];
    uint2 o;
    o.x = pack_h2(v.x * alpha, v.y * alpha);
    o.y = pack_h2(v.z * alpha, v.w * alpha);
    ((uint2*)dst)[i] = o;
}

__global__ void __launch_bounds__(256) cvt_inputs(const float* __restrict__ noisy,
                                                  const float* __restrict__ x) {
    const float* src = blockIdx.y ? x : noisy;
    __half* dst = blockIdx.y ? g_xh : g_nh;
    int i = blockIdx.x * 256 + threadIdx.x;          // kB*kT*kE/4 float4
    float4 v = ((const float4*)src)[i];
    uint2 o;
    o.x = pack_h2(v.x, v.y);
    o.y = pack_h2(v.z, v.w);
    ((uint2*)dst)[i] = o;
}

// ---------------------------------------------------------------------------
// lambda = exp(sum lq1*lk1) - exp(sum lq2*lk2) + LAMBDA_INIT
// ---------------------------------------------------------------------------
__global__ void lambda_kernel(const float* __restrict__ lq1, const float* __restrict__ lk1,
                              const float* __restrict__ lq2, const float* __restrict__ lk2) {
    int l = threadIdx.x;
    float a = lq1[l] * lk1[l] + lq1[l + 32] * lk1[l + 32];
    float b = lq2[l] * lk2[l] + lq2[l + 32] * lk2[l + 32];
#pragma unroll
    for (int o = 16; o; o >>= 1) {
        a += __shfl_xor_sync(0xffffffffu, a, o);
        b += __shfl_xor_sync(0xffffffffu, b, o);
    }
    if (l == 0) g_lambda = expf(a) - expf(b) + LAMBDA_INIT;
}

// ---------------------------------------------------------------------------
// fp16 GEMM: cp.async 3-buffer pipeline (depth-2 prefetch, ONE sync per slab)
// + ldmatrix + m16n8k16 HMMA (fp32 acc).
// C[m,n] = sum_k A[m,k] * W[n,k]; M=4096, N=1024, K=1024.
// 128x128 CTA tile, BK=64, 256 threads (8 warps 2x4, 64x32 warp tiles).
// smem layout: rows of 64 f16 (128B); 16B chunk c of row r stored at c^(r&7).
// ---------------------------------------------------------------------------
constexpr uint32_t GEMM_SMEM = 3 * 16384 * 2;   // 98304

template <bool HEADOUT>
__device__ __forceinline__ void mma_gemm_h(const __half* __restrict__ A,
                                           const __half* __restrict__ Wh,
                                           void* __restrict__ Oout) {
    extern __shared__ __align__(16) char dyn[];
    const int K = 1024;
    const uint32_t aS = (uint32_t)__cvta_generic_to_shared(dyn);
    const uint32_t bS = aS + 49152;       // 3 stages x 128x64 f16 = 49152 B

    int tid = threadIdx.x, lane = tid & 31, warp = tid >> 5;
    int g = lane >> 2, tg = lane & 3;
    int wm = warp >> 2, wn = warp & 3;
    int m0 = blockIdx.y * 128, n0 = blockIdx.x * 128;
    int sw = lane & 7;

    int arow = (lane & 7) + (((lane >> 3) & 1) << 3);
    int ahi  = (lane >> 4) & 1;
    int brow = (lane & 7) + (((lane >> 4) & 1) << 3);
    int bhi  = (lane >> 3) & 1;

    auto stage = [&](int s) {
        int f = s - (s / 3) * 3;
        uint32_t ab = aS + f * 16384;
        uint32_t bb = bS + f * 16384;
#pragma unroll
        for (int it = 0; it < 4; it++) {
            int ch = tid + it * 256;               // 1024 chunks per tile
            int r = ch >> 3, c = ch & 7;
            uint32_t so = r * 128 + ((c ^ (r & 7)) << 4);
            CP_ASYNC16(ab + so, A + (size_t)(m0 + r) * K + s * 64 + c * 8);
            CP_ASYNC16(bb + so, Wh + (size_t)(n0 + r) * K + s * 64 + c * 8);
        }
        CP_COMMIT();
    };

    float acc[4][4][4] = {};

    stage(0);
    stage(1);

    for (int i = 0; i < 16; i++) {
        if (i < 15) asm volatile("cp.async.wait_group 1;");
        else        asm volatile("cp.async.wait_group 0;");
        __syncthreads();               // buffer i visible to all; buffer (i+2)%3 free
        if (i + 2 < 16) stage(i + 2);

        int f = i - (i / 3) * 3;
        uint32_t ab = aS + f * 16384;
        uint32_t bb = bS + f * 16384;

#pragma unroll
        for (int kc = 0; kc < 4; kc++) {
            uint32_t af[4][4];
#pragma unroll
            for (int mt = 0; mt < 4; mt++) {
                uint32_t ad = ab + (64 * wm + 16 * mt + arow) * 128 +
                              (((2 * kc + ahi) ^ sw) << 4);
                ldsm_x4(af[mt][0], af[mt][1], af[mt][2], af[mt][3], ad);
            }
#pragma unroll
            for (int p = 0; p < 2; p++) {
                uint32_t bd = bb + (32 * wn + 16 * p + brow) * 128 +
                              (((2 * kc + bhi) ^ sw) << 4);
                uint32_t b0, b1, b2, b3;
                ldsm_x4(b0, b1, b2, b3, bd);
                uint32_t bfa[2] = {b0, b1}, bfb[2] = {b2, b3};
#pragma unroll
                for (int mt = 0; mt < 4; mt++) {
                    mma_f16(acc[mt][2 * p], af[mt], bfa);
                    mma_f16(acc[mt][2 * p + 1], af[mt], bfb);
                }
            }
        }
    }

#pragma unroll
    for (int mt = 0; mt < 4; mt++) {
        int r1 = m0 + 64 * wm + 16 * mt + g;
#pragma unroll
        for (int nt = 0; nt < 4; nt++) {
            int cc = n0 + 32 * wn + 8 * nt + 2 * tg;
            float c0 = acc[mt][nt][0], c1 = acc[mt][nt][1];
            float c2 = acc[mt][nt][2], c3 = acc[mt][nt][3];
            if (HEADOUT) {
                int b = r1 >> 11, t = r1 & 2047;
                int h = cc >> 6, d = cc & 63;
                __half* base = (__half*)Oout + ((size_t)(b * kH + h) * kT + t) * kD + d;
                *(uint32_t*)base = pack_h2(c0, c1);
                *(uint32_t*)(base + 8 * kD) = pack_h2(c2, c3);
            } else {
                float* O = (float*)Oout;
                *(float2*)(O + (size_t)r1 * 1024 + cc) = make_float2(c0, c1);
                *(float2*)(O + (size_t)(r1 + 8) * 1024 + cc) = make_float2(c2, c3);
            }
        }
    }
}

__global__ void __launch_bounds__(256) proj_gemm() {
    const __half* A; const __half* W; __half* O;
    switch (blockIdx.z) {
        case 0: A = g_nh; W = g_wq1; O = g_q1; break;   // QSCALE folded into g_wq1
        case 1: A = g_nh; W = g_wk1; O = g_k1; break;
        case 2: A = g_xh; W = g_wq2; O = g_q2; break;   // QSCALE folded into g_wq2
        case 3: A = g_xh; W = g_wk2; O = g_k2; break;
        default: A = g_nh; W = g_wv; O = g_v; break;
    }
    mma_gemm_h<true>(A, W, O);
}

__global__ void __launch_bounds__(256) out_gemm(float* __restrict__ out) {
    mma_gemm_h<false>(g_attn, g_wo, out);
}

// ---------------------------------------------------------------------------
// Fused differential attention: cp.async double-buffered K1/K2/V tiles,
// ldmatrix fragments (V via ldmatrix.trans), register-resident Q and P,
// MUFU ex2 for softmax numerators, l-sums via ones-column HMMA,
// fused RMSNorm epilogue. Grid (16 qtiles, 32 bh), 256 threads.
// ---------------------------------------------------------------------------
constexpr int AT_SMEM = 3 * 2 * 64 * 64 * 2;   // 49152 bytes

__global__ void __launch_bounds__(256) diffattn(const float* __restrict__ subln) {
    extern __shared__ __align__(16) char dyn[];
    const uint32_t k1S = (uint32_t)__cvta_generic_to_shared(dyn);
    const uint32_t k2S = k1S + 16384;
    const uint32_t vS  = k1S + 32768;

    int tid = threadIdx.x, lane = tid & 31, warp = tid >> 5;
    int g = lane >> 2, tg = lane & 3;
    int bh = blockIdx.y, qt = blockIdx.x;
    int sw = lane & 7;

    int brow = (lane & 7) + (((lane >> 4) & 1) << 3);
    int bhi  = (lane >> 3) & 1;
    int vrow = (lane & 7) + (((lane >> 3) & 1) << 3);
    int vhi  = (lane >> 4) & 1;

    // ---- Q fragments: registers for the whole CTA ----
    uint32_t aq1[4][4], aq2[4][4];
    {
        const uint32_t* q1p = (const uint32_t*)(g_q1 + ((size_t)bh * kT + qt * 128 + 16 * warp + g) * kD);
        const uint32_t* q2p = (const uint32_t*)(g_q2 + ((size_t)bh * kT + qt * 128 + 16 * warp + g) * kD);
        const uint32_t* q1p8 = q1p + 8 * 32;
        const uint32_t* q2p8 = q2p + 8 * 32;
#pragma unroll
        for (int k16 = 0; k16 < 4; k16++) {
            aq1[k16][0] = q1p [k16 * 8 + tg];
            aq1[k16][1] = q1p8[k16 * 8 + tg];
            aq1[k16][2] = q1p [k16 * 8 + tg + 4];
            aq1[k16][3] = q1p8[k16 * 8 + tg + 4];
            aq2[k16][0] = q2p [k16 * 8 + tg];
            aq2[k16][1] = q2p8[k16 * 8 + tg];
            aq2[k16][2] = q2p [k16 * 8 + tg + 4];
            aq2[k16][3] = q2p8[k16 * 8 + tg + 4];
        }
    }

    const __half* K1b = g_k1 + (size_t)bh * kT * kD;
    const __half* K2b = g_k2 + (size_t)bh * kT * kD;
    const __half* Vb  = g_v  + (size_t)bh * kT * kD;

    auto stage = [&](int kt, int buf) {
        uint32_t o = buf * 8192;
#pragma unroll
        for (int it = 0; it < 2; it++) {
            int ch = tid + it * 256;
            int r = ch >> 3, c = ch & 7;
            uint32_t so = o + r * 128 + ((c ^ (r & 7)) << 4);
            CP_ASYNC16(k1S + so, K1b + ((size_t)kt * 64 + r) * kD + c * 8);
            CP_ASYNC16(k2S + so, K2b + ((size_t)kt * 64 + r) * kD + c * 8);
            CP_ASYNC16(vS + so,  Vb  + ((size_t)kt * 64 + r) * kD + c * 8);
        }
    };

    float acc1[8][4] = {}, acc2[8][4] = {};
    float lacc1[4] = {}, lacc2[4] = {};
    const uint32_t onesf[2] = {0x3C003C00u, 0x3C003C00u};   // fp16 1.0 x4

    stage(0, 0);
    CP_COMMIT();

    for (int kt = 0; kt < 32; kt++) {
        if (kt < 31) {
            stage(kt + 1, (kt + 1) & 1);
            CP_COMMIT();
            asm volatile("cp.async.wait_group 1;");
        } else {
            asm volatile("cp.async.wait_group 0;");
        }
        __syncthreads();
        uint32_t o = (kt & 1) * 8192;
        uint32_t k1b = k1S + o, k2b = k2S + o, vb = vS + o;

        // ---- S = Q K^T (both branches), log2 domain ----
        float s1[8][4] = {}, s2[8][4] = {};
#pragma unroll
        for (int kc = 0; kc < 4; kc++) {
            uint32_t csel = ((2 * kc + bhi) ^ sw) << 4;
#pragma unroll
            for (int p = 0; p < 4; p++) {
                uint32_t roff = (16 * p + brow) * 128 + csel;
                uint32_t b0, b1, b2, b3;
                ldsm_x4(b0, b1, b2, b3, k1b + roff);
                uint32_t bfa[2] = {b0, b1}, bfb[2] = {b2, b3};
                mma_f16(s1[2 * p], aq1[kc], bfa);
                mma_f16(s1[2 * p + 1], aq1[kc], bfb);
                ldsm_x4(b0, b1, b2, b3, k2b + roff);
                uint32_t bfc[2] = {b0, b1}, bfd[2] = {b2, b3};
                mma_f16(s2[2 * p], aq2[kc], bfc);
                mma_f16(s2[2 * p + 1], aq2[kc], bfd);
            }
        }

        // ---- exp2 via MUFU, pack P into PV A-fragments (registers only) ----
        uint32_t pu1[8][2], pu2[8][2];
#pragma unroll
        for (int nt = 0; nt < 8; nt++) {
            pu1[nt][0] = pack_h2(ex2f(s1[nt][0]), ex2f(s1[nt][1]));
            pu1[nt][1] = pack_h2(ex2f(s1[nt][2]), ex2f(s1[nt][3]));
            pu2[nt][0] = pack_h2(ex2f(s2[nt][0]), ex2f(s2[nt][1]));
            pu2[nt][1] = pack_h2(ex2f(s2[nt][2]), ex2f(s2[nt][3]));
        }

        // ---- acc += P @ V; l += P @ ones (constant B fragment, no smem) ----
#pragma unroll
        for (int j = 0; j < 4; j++) {
            uint32_t A1[4] = {pu1[2 * j][0], pu1[2 * j][1], pu1[2 * j + 1][0], pu1[2 * j + 1][1]};
            uint32_t A2[4] = {pu2[2 * j][0], pu2[2 * j][1], pu2[2 * j + 1][0], pu2[2 * j + 1][1]};
            mma_f16(lacc1, A1, onesf);
            mma_f16(lacc2, A2, onesf);
            uint32_t rbase = vb + (16 * j + vrow) * 128;
#pragma unroll
            for (int p = 0; p < 4; p++) {
                uint32_t b0, b1, b2, b3;
                ldsm_x4_t(b0, b1, b2, b3, rbase + (((2 * p + vhi) ^ sw) << 4));
                uint32_t bfa[2] = {b0, b1}, bfb[2] = {b2, b3};
                mma_f16(acc1[2 * p], A1, bfa);
                mma_f16(acc1[2 * p + 1], A1, bfb);
                mma_f16(acc2[2 * p], A2, bfa);
                mma_f16(acc2[2 * p + 1], A2, bfb);
            }
        }
        __syncthreads();
    }

    // ---- epilogue: normalize, combine, RMSNorm, affine, write fp16 ----
    float i1a = 1.0f / lacc1[0], i1b = 1.0f / lacc1[2];
    float i2a = 1.0f / lacc2[0], i2b = 1.0f / lacc2[2];
    float lam = g_lambda;

    float ossa = 0.f, ossb = 0.f;
#pragma unroll
    for (int ntd = 0; ntd < 8; ntd++) {
        float v0 = acc1[ntd][0] * i1a - lam * (acc2[ntd][0] * i2a);
        float v1 = acc1[ntd][1] * i1a - lam * (acc2[ntd][1] * i2a);
        float v2 = acc1[ntd][2] * i1b - lam * (acc2[ntd][2] * i2b);
        float v3 = acc1[ntd][3] * i1b - lam * (acc2[ntd][3] * i2b);
        acc1[ntd][0] = v0; acc1[ntd][1] = v1; acc1[ntd][2] = v2; acc1[ntd][3] = v3;
        ossa += v0 * v0 + v1 * v1;
        ossb += v2 * v2 + v3 * v3;
    }
    ossa += __shfl_xor_sync(0xffffffffu, ossa, 1); ossa += __shfl_xor_sync(0xffffffffu, ossa, 2);
    ossb += __shfl_xor_sync(0xffffffffu, ossb, 1); ossb += __shfl_xor_sync(0xffffffffu, ossb, 2);
    float sca = rsqrtf(ossa * (1.0f / 64.0f) + EPS) * (1.0f - LAMBDA_INIT);
    float scb = rsqrtf(ossb * (1.0f / 64.0f) + EPS) * (1.0f - LAMBDA_INIT);

    int b = bh >> 4, h = bh & 15;
    int t = qt * 128 + 16 * warp + g;
    __half* base = g_attn + ((size_t)(b * kT + t) * kH + h) * kD;
#pragma unroll
    for (int ntd = 0; ntd < 8; ntd++) {
        int d0 = 8 * ntd + 2 * tg;
        float w0 = subln[d0], w1 = subln[d0 + 1];
        *(uint32_t*)(base + d0) = pack_h2(acc1[ntd][0] * sca * w0, acc1[ntd][1] * sca * w1);
        *(uint32_t*)(base + 8 * kH * kD + d0) = pack_h2(acc1[ntd][2] * scb * w0, acc1[ntd][3] * scb * w1);
    }
}

// ---------------------------------------------------------------------------
extern "C" void kernel_launch(void* const* d_in, const int* in_sizes, int n_in,
                              void* d_out, int out_size) {
    const float* noisy = (const float*)d_in[0];
    const float* x     = (const float*)d_in[1];
    const float* Wq1   = (const float*)d_in[2];
    const float* Wk1   = (const float*)d_in[3];
    const float* Wq2   = (const float*)d_in[4];
    const float* Wk2   = (const float*)d_in[5];
    const float* Wv    = (const float*)d_in[6];
    const float* Wout  = (const float*)d_in[7];
    const float* lq1   = (const float*)d_in[8];
    const float* lk1   = (const float*)d_in[9];
    const float* lq2   = (const float*)d_in[10];
    const float* lk2   = (const float*)d_in[11];
    const float* subln = (const float*)d_in[12];
    float* out = (float*)d_out;

    cudaFuncSetAttribute(proj_gemm, cudaFuncAttributeMaxDynamicSharedMemorySize, GEMM_SMEM);
    cudaFuncSetAttribute(out_gemm, cudaFuncAttributeMaxDynamicSharedMemorySize, GEMM_SMEM);
    cudaFuncSetAttribute(diffattn, cudaFuncAttributeMaxDynamicSharedMemorySize, AT_SMEM);

    cvt_inputs<<<dim3(4096, 2), 256>>>(noisy, x);
    cvt_weights<<<dim3(1024, 6), 256>>>(Wq1, Wk1, Wq2, Wk2, Wv, Wout);
    lambda_kernel<<<1, 32>>>(lq1, lk1, lq2, lk2);
    proj_gemm<<<dim3(8, 32, 5), 256, GEMM_SMEM>>>();
    diffattn<<<dim3(16, 32), 256, AT_SMEM>>>(subln);
    out_gemm<<<dim3(8, 32), 256, GEMM_SMEM>>>(out);
}

// round 13
// speedup vs baseline: 10.8639x; 1.0869x over previous
#include <cuda_runtime.h>
#include <cuda_fp16.h>
#include <math.h>
#include <stdint.h>

// Problem constants
constexpr int kB = 2, kT = 2048, kE = 1024, kH = 16, kD = 64;
constexpr float LAMBDA_INIT = 0.47071301834358415f;   // 0.8 - 0.6*exp(-0.6)
constexpr float LOG2E       = 1.4426950408889634f;
constexpr float QSCALE      = 0.125f * LOG2E;         // D^-0.5 folded with log2e
constexpr float EPS         = 1e-5f;

// Scratch (device globals; allocation is forbidden)
__device__ __half g_q1[kB * kH * kT * kD];
__device__ __half g_k1[kB * kH * kT * kD];
__device__ __half g_q2[kB * kH * kT * kD];
__device__ __half g_k2[kB * kH * kT * kD];
__device__ __half g_v [kB * kH * kT * kD];
__device__ __half g_attn[kB * kT * kE];
__device__ __half g_nh[kB * kT * kE];
__device__ __half g_xh[kB * kT * kE];
__device__ __half g_wq1[kE * kE], g_wk1[kE * kE], g_wq2[kE * kE];
__device__ __half g_wk2[kE * kE], g_wv[kE * kE], g_wo[kE * kE];
__device__ float g_pv1[kB * kH * kT * kD];   // unnormalized P1@V
__device__ float g_pv2[kB * kH * kT * kD];   // unnormalized P2@V
__device__ float g_l1[kB * kH * kT];         // softmax denominators
__device__ float g_l2[kB * kH * kT];
__device__ float g_lambda;

// ---------------------------------------------------------------------------
// helpers
// ---------------------------------------------------------------------------
__device__ __forceinline__ uint32_t pack_h2(float a, float b) {
    __half2 h = __floats2half2_rn(a, b);
    return *reinterpret_cast<uint32_t*>(&h);
}

__device__ __forceinline__ float ex2f(float x) {
    float r;
    asm("ex2.approx.ftz.f32 %0, %1;" : "=f"(r) : "f"(x));
    return r;
}

__device__ __forceinline__ void mma_f16(float* c, const uint32_t* a, const uint32_t* b) {
    asm volatile(
        "mma.sync.aligned.m16n8k16.row.col.f32.f16.f16.f32 "
        "{%0,%1,%2,%3}, {%4,%5,%6,%7}, {%8,%9}, {%0,%1,%2,%3};"
        : "+f"(c[0]), "+f"(c[1]), "+f"(c[2]), "+f"(c[3])
        : "r"(a[0]), "r"(a[1]), "r"(a[2]), "r"(a[3]), "r"(b[0]), "r"(b[1]));
}

__device__ __forceinline__ void ldsm_x4(uint32_t& r0, uint32_t& r1, uint32_t& r2,
                                        uint32_t& r3, uint32_t addr) {
    asm volatile("ldmatrix.sync.aligned.m8n8.x4.shared.b16 {%0,%1,%2,%3}, [%4];"
                 : "=r"(r0), "=r"(r1), "=r"(r2), "=r"(r3) : "r"(addr));
}

__device__ __forceinline__ void ldsm_x4_t(uint32_t& r0, uint32_t& r1, uint32_t& r2,
                                          uint32_t& r3, uint32_t addr) {
    asm volatile("ldmatrix.sync.aligned.m8n8.x4.trans.shared.b16 {%0,%1,%2,%3}, [%4];"
                 : "=r"(r0), "=r"(r1), "=r"(r2), "=r"(r3) : "r"(addr));
}

#define CP_ASYNC16(dst, src) \
    asm volatile("cp.async.cg.shared.global [%0], [%1], 16;" :: "r"(dst), "l"(src))
#define CP_COMMIT() asm volatile("cp.async.commit_group;")

// ---------------------------------------------------------------------------
// All fp32 -> fp16 conversions in ONE launch.
// blocks [0,8192): inputs (noisy, x); blocks [8192,14336): 6 weights.
// ---------------------------------------------------------------------------
__global__ void __launch_bounds__(256) cvt_all(
    const float* __restrict__ noisy, const float* __restrict__ x,
    const float* __restrict__ Wq1, const float* __restrict__ Wk1,
    const float* __restrict__ Wq2, const float* __restrict__ Wk2,
    const float* __restrict__ Wv, const float* __restrict__ Wo) {
    int bid = blockIdx.x;
    const float* src; __half* dst; float alpha = 1.0f; int i;
    if (bid < 8192) {
        src = (bid < 4096) ? noisy : x;
        dst = (bid < 4096) ? g_nh : g_xh;
        i = (bid & 4095) * 256 + threadIdx.x;
    } else {
        int wb = bid - 8192;
        switch (wb >> 10) {
            case 0: src = Wq1; dst = g_wq1; alpha = QSCALE; break;
            case 1: src = Wk1; dst = g_wk1; break;
            case 2: src = Wq2; dst = g_wq2; alpha = QSCALE; break;
            case 3: src = Wk2; dst = g_wk2; break;
            case 4: src = Wv;  dst = g_wv;  break;
            default: src = Wo; dst = g_wo;  break;
        }
        i = (wb & 1023) * 256 + threadIdx.x;
    }
    float4 v = ((const float4*)src)[i];
    uint2 o;
    o.x = pack_h2(v.x * alpha, v.y * alpha);
    o.y = pack_h2(v.z * alpha, v.w * alpha);
    ((uint2*)dst)[i] = o;
}

// ---------------------------------------------------------------------------
// lambda = exp(sum lq1*lk1) - exp(sum lq2*lk2) + LAMBDA_INIT
// ---------------------------------------------------------------------------
__global__ void lambda_kernel(const float* __restrict__ lq1, const float* __restrict__ lk1,
                              const float* __restrict__ lq2, const float* __restrict__ lk2) {
    int l = threadIdx.x;
    float a = lq1[l] * lk1[l] + lq1[l + 32] * lk1[l + 32];
    float b = lq2[l] * lk2[l] + lq2[l + 32] * lk2[l + 32];
#pragma unroll
    for (int o = 16; o; o >>= 1) {
        a += __shfl_xor_sync(0xffffffffu, a, o);
        b += __shfl_xor_sync(0xffffffffu, b, o);
    }
    if (l == 0) g_lambda = expf(a) - expf(b) + LAMBDA_INIT;
}

// ---------------------------------------------------------------------------
// fp16 GEMM: 2-stage cp.async (64KB smem -> 2 CTAs/SM) + ldmatrix + HMMA.
// C[m,n] = sum_k A[m,k] * W[n,k]; M=4096, N=1024, K=1024.
// 128x128 CTA tile, BK=64, 256 threads (8 warps 2x4, 64x32 warp tiles).
// smem: rows of 64 f16 (128B); 16B chunk c of row r stored at c^(r&7).
// ---------------------------------------------------------------------------
constexpr uint32_t GEMM_SMEM = 2 * 16384 * 2;   // 65536

template <bool HEADOUT>
__device__ __forceinline__ void mma_gemm_h(const __half* __restrict__ A,
                                           const __half* __restrict__ Wh,
                                           void* __restrict__ Oout) {
    extern __shared__ __align__(16) char dyn[];
    const int K = 1024;
    const uint32_t aS = (uint32_t)__cvta_generic_to_shared(dyn);
    const uint32_t bS = aS + 32768;       // 2 stages x 128x64 f16

    int tid = threadIdx.x, lane = tid & 31, warp = tid >> 5;
    int g = lane >> 2, tg = lane & 3;
    int wm = warp >> 2, wn = warp & 3;
    int m0 = blockIdx.y * 128, n0 = blockIdx.x * 128;
    int sw = lane & 7;

    int arow = (lane & 7) + (((lane >> 3) & 1) << 3);
    int ahi  = (lane >> 4) & 1;
    int brow = (lane & 7) + (((lane >> 4) & 1) << 3);
    int bhi  = (lane >> 3) & 1;

    auto stage = [&](int s) {
        int f = s & 1;
        uint32_t ab = aS + f * 16384;
        uint32_t bb = bS + f * 16384;
#pragma unroll
        for (int it = 0; it < 4; it++) {
            int ch = tid + it * 256;               // 1024 chunks per tile
            int r = ch >> 3, c = ch & 7;
            uint32_t so = r * 128 + ((c ^ (r & 7)) << 4);
            CP_ASYNC16(ab + so, A + (size_t)(m0 + r) * K + s * 64 + c * 8);
            CP_ASYNC16(bb + so, Wh + (size_t)(n0 + r) * K + s * 64 + c * 8);
        }
        CP_COMMIT();
    };

    float acc[4][4][4] = {};

    stage(0);
    stage(1);

    for (int i = 0; i < 16; i++) {
        if (i < 15) asm volatile("cp.async.wait_group 1;");
        else        asm volatile("cp.async.wait_group 0;");
        __syncthreads();               // buffer i visible to all warps

        int f = i & 1;
        uint32_t ab = aS + f * 16384;
        uint32_t bb = bS + f * 16384;

#pragma unroll
        for (int kc = 0; kc < 4; kc++) {
            uint32_t af[4][4];
#pragma unroll
            for (int mt = 0; mt < 4; mt++) {
                uint32_t ad = ab + (64 * wm + 16 * mt + arow) * 128 +
                              (((2 * kc + ahi) ^ sw) << 4);
                ldsm_x4(af[mt][0], af[mt][1], af[mt][2], af[mt][3], ad);
            }
#pragma unroll
            for (int p = 0; p < 2; p++) {
                uint32_t bd = bb + (32 * wn + 16 * p + brow) * 128 +
                              (((2 * kc + bhi) ^ sw) << 4);
                uint32_t b0, b1, b2, b3;
                ldsm_x4(b0, b1, b2, b3, bd);
                uint32_t bfa[2] = {b0, b1}, bfb[2] = {b2, b3};
#pragma unroll
                for (int mt = 0; mt < 4; mt++) {
                    mma_f16(acc[mt][2 * p], af[mt], bfa);
                    mma_f16(acc[mt][2 * p + 1], af[mt], bfb);
                }
            }
        }

        if (i + 2 < 16) {
            __syncthreads();           // all warps done reading buffer f
            stage(i + 2);              // refill it
        }
    }

#pragma unroll
    for (int mt = 0; mt < 4; mt++) {
        int r1 = m0 + 64 * wm + 16 * mt + g;
#pragma unroll
        for (int nt = 0; nt < 4; nt++) {
            int cc = n0 + 32 * wn + 8 * nt + 2 * tg;
            float c0 = acc[mt][nt][0], c1 = acc[mt][nt][1];
            float c2 = acc[mt][nt][2], c3 = acc[mt][nt][3];
            if (HEADOUT) {
                int b = r1 >> 11, t = r1 & 2047;
                int h = cc >> 6, d = cc & 63;
                __half* base = (__half*)Oout + ((size_t)(b * kH + h) * kT + t) * kD + d;
                *(uint32_t*)base = pack_h2(c0, c1);
                *(uint32_t*)(base + 8 * kD) = pack_h2(c2, c3);
            } else {
                float* O = (float*)Oout;
                *(float2*)(O + (size_t)r1 * 1024 + cc) = make_float2(c0, c1);
                *(float2*)(O + (size_t)(r1 + 8) * 1024 + cc) = make_float2(c2, c3);
            }
        }
    }
}

__global__ void __launch_bounds__(256, 2) proj_gemm() {
    const __half* A; const __half* W; __half* O;
    switch (blockIdx.z) {
        case 0: A = g_nh; W = g_wq1; O = g_q1; break;   // QSCALE folded into g_wq1
        case 1: A = g_nh; W = g_wk1; O = g_k1; break;
        case 2: A = g_xh; W = g_wq2; O = g_q2; break;   // QSCALE folded into g_wq2
        case 3: A = g_xh; W = g_wk2; O = g_k2; break;
        default: A = g_nh; W = g_wv; O = g_v; break;
    }
    mma_gemm_h<true>(A, W, O);
}

__global__ void __launch_bounds__(256, 2) out_gemm(float* __restrict__ out) {
    mma_gemm_h<false>(g_attn, g_wo, out);
}

// ---------------------------------------------------------------------------
// Single-branch attention: computes unnormalized P_z @ V (fp32) + row sums.
// blockIdx.z selects branch (0: q1/k1, 1: q2/k2). Halved register pressure
// -> __launch_bounds__(256,2) for 2 CTAs/SM; grid (16,32,2) = 1024 CTAs.
// cp.async double-buffered K/V, ldmatrix fragments, MUFU ex2,
// l-sums via ones-column HMMA.
// ---------------------------------------------------------------------------
constexpr int ATB_SMEM = 2 * 2 * 64 * 64 * 2;   // 32768 bytes (K + V, 2 stages)

__global__ void __launch_bounds__(256, 2) diffattn_branch() {
    extern __shared__ __align__(16) char dyn[];
    const uint32_t kS = (uint32_t)__cvta_generic_to_shared(dyn);
    const uint32_t vS = kS + 16384;

    int tid = threadIdx.x, lane = tid & 31, warp = tid >> 5;
    int g = lane >> 2, tg = lane & 3;
    int bh = blockIdx.y, qt = blockIdx.x, z = blockIdx.z;
    int sw = lane & 7;

    int brow = (lane & 7) + (((lane >> 4) & 1) << 3);
    int bhi  = (lane >> 3) & 1;
    int vrow = (lane & 7) + (((lane >> 3) & 1) << 3);
    int vhi  = (lane >> 4) & 1;

    const __half* Qg = (z ? g_q2 : g_q1) + ((size_t)bh * kT + qt * 128 + 16 * warp + g) * kD;
    const __half* Kb = (z ? g_k2 : g_k1) + (size_t)bh * kT * kD;
    const __half* Vb = g_v + (size_t)bh * kT * kD;
    float* pv = z ? g_pv2 : g_pv1;
    float* lv = z ? g_l2 : g_l1;

    // ---- Q fragments: registers for the whole CTA ----
    uint32_t aq[4][4];
    {
        const uint32_t* qp = (const uint32_t*)Qg;
        const uint32_t* qp8 = qp + 8 * 32;
#pragma unroll
        for (int k16 = 0; k16 < 4; k16++) {
            aq[k16][0] = qp [k16 * 8 + tg];
            aq[k16][1] = qp8[k16 * 8 + tg];
            aq[k16][2] = qp [k16 * 8 + tg + 4];
            aq[k16][3] = qp8[k16 * 8 + tg + 4];
        }
    }

    auto stage = [&](int kt, int buf) {
        uint32_t o = buf * 8192;
#pragma unroll
        for (int it = 0; it < 2; it++) {
            int ch = tid + it * 256;
            int r = ch >> 3, c = ch & 7;
            uint32_t so = o + r * 128 + ((c ^ (r & 7)) << 4);
            CP_ASYNC16(kS + so, Kb + ((size_t)kt * 64 + r) * kD + c * 8);
            CP_ASYNC16(vS + so, Vb + ((size_t)kt * 64 + r) * kD + c * 8);
        }
    };

    float acc[8][4] = {};
    float lacc[4] = {};
    const uint32_t onesf[2] = {0x3C003C00u, 0x3C003C00u};   // fp16 1.0 x4

    stage(0, 0);
    CP_COMMIT();

    for (int kt = 0; kt < 32; kt++) {
        if (kt < 31) {
            stage(kt + 1, (kt + 1) & 1);
            CP_COMMIT();
            asm volatile("cp.async.wait_group 1;");
        } else {
            asm volatile("cp.async.wait_group 0;");
        }
        __syncthreads();
        uint32_t o = (kt & 1) * 8192;
        uint32_t kb = kS + o, vb = vS + o;

        // ---- S = Q K^T (log2 domain) ----
        float s[8][4] = {};
#pragma unroll
        for (int kc = 0; kc < 4; kc++) {
            uint32_t csel = ((2 * kc + bhi) ^ sw) << 4;
#pragma unroll
            for (int p = 0; p < 4; p++) {
                uint32_t b0, b1, b2, b3;
                ldsm_x4(b0, b1, b2, b3, kb + (16 * p + brow) * 128 + csel);
                uint32_t bfa[2] = {b0, b1}, bfb[2] = {b2, b3};
                mma_f16(s[2 * p], aq[kc], bfa);
                mma_f16(s[2 * p + 1], aq[kc], bfb);
            }
        }

        // ---- exp2 via MUFU, pack P into PV A-fragments ----
        uint32_t pu[8][2];
#pragma unroll
        for (int nt = 0; nt < 8; nt++) {
            pu[nt][0] = pack_h2(ex2f(s[nt][0]), ex2f(s[nt][1]));
            pu[nt][1] = pack_h2(ex2f(s[nt][2]), ex2f(s[nt][3]));
        }

        // ---- acc += P @ V; l += P @ ones ----
#pragma unroll
        for (int j = 0; j < 4; j++) {
            uint32_t A1[4] = {pu[2 * j][0], pu[2 * j][1], pu[2 * j + 1][0], pu[2 * j + 1][1]};
            mma_f16(lacc, A1, onesf);
            uint32_t rbase = vb + (16 * j + vrow) * 128;
#pragma unroll
            for (int p = 0; p < 4; p++) {
                uint32_t b0, b1, b2, b3;
                ldsm_x4_t(b0, b1, b2, b3, rbase + (((2 * p + vhi) ^ sw) << 4));
                uint32_t bfa[2] = {b0, b1}, bfb[2] = {b2, b3};
                mma_f16(acc[2 * p], A1, bfa);
                mma_f16(acc[2 * p + 1], A1, bfb);
            }
        }
        __syncthreads();
    }

    // ---- write unnormalized PV (fp32) and denominators ----
    int t = qt * 128 + 16 * warp + g;
    float* dst = pv + ((size_t)bh * kT + t) * kD;
#pragma unroll
    for (int ntd = 0; ntd < 8; ntd++) {
        int d0 = 8 * ntd + 2 * tg;
        *(float2*)(dst + d0) = make_float2(acc[ntd][0], acc[ntd][1]);
        *(float2*)(dst + 8 * kD + d0) = make_float2(acc[ntd][2], acc[ntd][3]);
    }
    if (tg == 0) {
        lv[(size_t)bh * kT + t] = lacc[0];
        lv[(size_t)bh * kT + t + 8] = lacc[2];
    }
}

// ---------------------------------------------------------------------------
// Combine: out = a1/l1 - lambda*a2/l2, RMSNorm over D, affine, (1-lam_init),
// write fp16 into [B,T,H,D] for the output GEMM. One warp per (bh,t) row.
// ---------------------------------------------------------------------------
__global__ void __launch_bounds__(256) combine(const float* __restrict__ subln) {
    int row = blockIdx.x * 8 + (threadIdx.x >> 5);   // over B*H*T = 65536
    int lane = threadIdx.x & 31;
    int bh = row >> 11, t = row & 2047;

    float i1 = 1.0f / g_l1[row];
    float i2 = 1.0f / g_l2[row];
    float lam = g_lambda;

    float2 a1 = ((const float2*)g_pv1)[(size_t)row * 32 + lane];
    float2 a2 = ((const float2*)g_pv2)[(size_t)row * 32 + lane];
    float v0 = a1.x * i1 - lam * (a2.x * i2);
    float v1 = a1.y * i1 - lam * (a2.y * i2);

    float ss = v0 * v0 + v1 * v1;
#pragma unroll
    for (int o = 16; o; o >>= 1) ss += __shfl_xor_sync(0xffffffffu, ss, o);
    float sc = rsqrtf(ss * (1.0f / 64.0f) + EPS) * (1.0f - LAMBDA_INIT);

    int d0 = 2 * lane;
    float w0 = subln[d0], w1 = subln[d0 + 1];
    int b = bh >> 4, h = bh & 15;
    __half* base = g_attn + ((size_t)(b * kT + t) * kH + h) * kD + d0;
    *(uint32_t*)base = pack_h2(v0 * sc * w0, v1 * sc * w1);
}

// ---------------------------------------------------------------------------
extern "C" void kernel_launch(void* const* d_in, const int* in_sizes, int n_in,
                              void* d_out, int out_size) {
    const float* noisy = (const float*)d_in[0];
    const float* x     = (const float*)d_in[1];
    const float* Wq1   = (const float*)d_in[2];
    const float* Wk1   = (const float*)d_in[3];
    const float* Wq2   = (const float*)d_in[4];
    const float* Wk2   = (const float*)d_in[5];
    const float* Wv    = (const float*)d_in[6];
    const float* Wout  = (const float*)d_in[7];
    const float* lq1   = (const float*)d_in[8];
    const float* lk1   = (const float*)d_in[9];
    const float* lq2   = (const float*)d_in[10];
    const float* lk2   = (const float*)d_in[11];
    const float* subln = (const float*)d_in[12];
    float* out = (float*)d_out;

    cudaFuncSetAttribute(proj_gemm, cudaFuncAttributeMaxDynamicSharedMemorySize, GEMM_SMEM);
    cudaFuncSetAttribute(out_gemm, cudaFuncAttributeMaxDynamicSharedMemorySize, GEMM_SMEM);
    cudaFuncSetAttribute(diffattn_branch, cudaFuncAttributeMaxDynamicSharedMemorySize, ATB_SMEM);

    cvt_all<<<14336, 256>>>(noisy, x, Wq1, Wk1, Wq2, Wk2, Wv, Wout);
    lambda_kernel<<<1, 32>>>(lq1, lk1, lq2, lk2);
    proj_gemm<<<dim3(8, 32, 5), 256, GEMM_SMEM>>>();
    diffattn_branch<<<dim3(16, 32, 2), 256, ATB_SMEM>>>();
    combine<<<8192, 256>>>(subln);
    out_gemm<<<dim3(8, 32), 256, GEMM_SMEM>>>(out);
}

// round 14
// speedup vs baseline: 11.5403x; 1.0623x over previous
#include <cuda_runtime.h>
#include <cuda_fp16.h>
#include <math.h>
#include <stdint.h>

// Problem constants
constexpr int kB = 2, kT = 2048, kE = 1024, kH = 16, kD = 64;
constexpr float LAMBDA_INIT = 0.47071301834358415f;   // 0.8 - 0.6*exp(-0.6)
constexpr float LOG2E       = 1.4426950408889634f;
constexpr float QSCALE      = 0.125f * LOG2E;         // D^-0.5 folded with log2e
constexpr float EPS         = 1e-5f;

// Scratch (device globals; allocation is forbidden)
__device__ __half g_q1[kB * kH * kT * kD];
__device__ __half g_k1[kB * kH * kT * kD];
__device__ __half g_q2[kB * kH * kT * kD];
__device__ __half g_k2[kB * kH * kT * kD];
__device__ __half g_v [kB * kH * kT * kD];
__device__ __half g_attn[kB * kT * kE];
__device__ __half g_nh[kB * kT * kE];
__device__ __half g_xh[kB * kT * kE];
__device__ __half g_wq1[kE * kE], g_wk1[kE * kE], g_wq2[kE * kE];
__device__ __half g_wk2[kE * kE], g_wv[kE * kE], g_wo[kE * kE];
__device__ float g_pv1[kB * kH * kT * kD];   // unnormalized P1@V
__device__ float g_pv2[kB * kH * kT * kD];   // unnormalized P2@V
__device__ float g_l1[kB * kH * kT];         // softmax denominators
__device__ float g_l2[kB * kH * kT];
__device__ float g_lambda;

// ---------------------------------------------------------------------------
// helpers
// ---------------------------------------------------------------------------
__device__ __forceinline__ uint32_t pack_h2(float a, float b) {
    __half2 h = __floats2half2_rn(a, b);
    return *reinterpret_cast<uint32_t*>(&h);
}

__device__ __forceinline__ float ex2f(float x) {
    float r;
    asm("ex2.approx.ftz.f32 %0, %1;" : "=f"(r) : "f"(x));
    return r;
}

__device__ __forceinline__ void mma_f16(float* c, const uint32_t* a, const uint32_t* b) {
    asm volatile(
        "mma.sync.aligned.m16n8k16.row.col.f32.f16.f16.f32 "
        "{%0,%1,%2,%3}, {%4,%5,%6,%7}, {%8,%9}, {%0,%1,%2,%3};"
        : "+f"(c[0]), "+f"(c[1]), "+f"(c[2]), "+f"(c[3])
        : "r"(a[0]), "r"(a[1]), "r"(a[2]), "r"(a[3]), "r"(b[0]), "r"(b[1]));
}

__device__ __forceinline__ void ldsm_x4(uint32_t& r0, uint32_t& r1, uint32_t& r2,
                                        uint32_t& r3, uint32_t addr) {
    asm volatile("ldmatrix.sync.aligned.m8n8.x4.shared.b16 {%0,%1,%2,%3}, [%4];"
                 : "=r"(r0), "=r"(r1), "=r"(r2), "=r"(r3) : "r"(addr));
}

__device__ __forceinline__ void ldsm_x4_t(uint32_t& r0, uint32_t& r1, uint32_t& r2,
                                          uint32_t& r3, uint32_t addr) {
    asm volatile("ldmatrix.sync.aligned.m8n8.x4.trans.shared.b16 {%0,%1,%2,%3}, [%4];"
                 : "=r"(r0), "=r"(r1), "=r"(r2), "=r"(r3) : "r"(addr));
}

#define CP_ASYNC16(dst, src) \
    asm volatile("cp.async.cg.shared.global [%0], [%1], 16;" :: "r"(dst), "l"(src))
#define CP_COMMIT() asm volatile("cp.async.commit_group;")

// ---------------------------------------------------------------------------
// All fp32 -> fp16 conversions in ONE launch.
// ---------------------------------------------------------------------------
__global__ void __launch_bounds__(256) cvt_all(
    const float* __restrict__ noisy, const float* __restrict__ x,
    const float* __restrict__ Wq1, const float* __restrict__ Wk1,
    const float* __restrict__ Wq2, const float* __restrict__ Wk2,
    const float* __restrict__ Wv, const float* __restrict__ Wo) {
    int bid = blockIdx.x;
    const float* src; __half* dst; float alpha = 1.0f; int i;
    if (bid < 8192) {
        src = (bid < 4096) ? noisy : x;
        dst = (bid < 4096) ? g_nh : g_xh;
        i = (bid & 4095) * 256 + threadIdx.x;
    } else {
        int wb = bid - 8192;
        switch (wb >> 10) {
            case 0: src = Wq1; dst = g_wq1; alpha = QSCALE; break;
            case 1: src = Wk1; dst = g_wk1; break;
            case 2: src = Wq2; dst = g_wq2; alpha = QSCALE; break;
            case 3: src = Wk2; dst = g_wk2; break;
            case 4: src = Wv;  dst = g_wv;  break;
            default: src = Wo; dst = g_wo;  break;
        }
        i = (wb & 1023) * 256 + threadIdx.x;
    }
    float4 v = ((const float4*)src)[i];
    uint2 o;
    o.x = pack_h2(v.x * alpha, v.y * alpha);
    o.y = pack_h2(v.z * alpha, v.w * alpha);
    ((uint2*)dst)[i] = o;
}

// ---------------------------------------------------------------------------
// lambda = exp(sum lq1*lk1) - exp(sum lq2*lk2) + LAMBDA_INIT
// ---------------------------------------------------------------------------
__global__ void lambda_kernel(const float* __restrict__ lq1, const float* __restrict__ lk1,
                              const float* __restrict__ lq2, const float* __restrict__ lk2) {
    int l = threadIdx.x;
    float a = lq1[l] * lk1[l] + lq1[l + 32] * lk1[l + 32];
    float b = lq2[l] * lk2[l] + lq2[l + 32] * lk2[l + 32];
#pragma unroll
    for (int o = 16; o; o >>= 1) {
        a += __shfl_xor_sync(0xffffffffu, a, o);
        b += __shfl_xor_sync(0xffffffffu, b, o);
    }
    if (l == 0) g_lambda = expf(a) - expf(b) + LAMBDA_INIT;
}

// ---------------------------------------------------------------------------
// fp16 GEMM: 2-stage cp.async (64KB smem -> 2 CTAs/SM) + ldmatrix + HMMA.
// C[m,n] = sum_k A[m,k] * W[n,k]; M=4096, N=1024, K=1024.
// 128x128 CTA tile, BK=64, 256 threads (8 warps 2x4, 64x32 warp tiles).
// ---------------------------------------------------------------------------
constexpr uint32_t GEMM_SMEM = 2 * 16384 * 2;   // 65536

template <bool HEADOUT>
__device__ __forceinline__ void mma_gemm_h(const __half* __restrict__ A,
                                           const __half* __restrict__ Wh,
                                           void* __restrict__ Oout) {
    extern __shared__ __align__(16) char dyn[];
    const int K = 1024;
    const uint32_t aS = (uint32_t)__cvta_generic_to_shared(dyn);
    const uint32_t bS = aS + 32768;

    int tid = threadIdx.x, lane = tid & 31, warp = tid >> 5;
    int g = lane >> 2, tg = lane & 3;
    int wm = warp >> 2, wn = warp & 3;
    int m0 = blockIdx.y * 128, n0 = blockIdx.x * 128;
    int sw = lane & 7;

    int arow = (lane & 7) + (((lane >> 3) & 1) << 3);
    int ahi  = (lane >> 4) & 1;
    int brow = (lane & 7) + (((lane >> 4) & 1) << 3);
    int bhi  = (lane >> 3) & 1;

    auto stage = [&](int s) {
        int f = s & 1;
        uint32_t ab = aS + f * 16384;
        uint32_t bb = bS + f * 16384;
#pragma unroll
        for (int it = 0; it < 4; it++) {
            int ch = tid + it * 256;
            int r = ch >> 3, c = ch & 7;
            uint32_t so = r * 128 + ((c ^ (r & 7)) << 4);
            CP_ASYNC16(ab + so, A + (size_t)(m0 + r) * K + s * 64 + c * 8);
            CP_ASYNC16(bb + so, Wh + (size_t)(n0 + r) * K + s * 64 + c * 8);
        }
        CP_COMMIT();
    };

    float acc[4][4][4] = {};

    stage(0);
    stage(1);

    for (int i = 0; i < 16; i++) {
        if (i < 15) asm volatile("cp.async.wait_group 1;");
        else        asm volatile("cp.async.wait_group 0;");
        __syncthreads();

        int f = i & 1;
        uint32_t ab = aS + f * 16384;
        uint32_t bb = bS + f * 16384;

#pragma unroll
        for (int kc = 0; kc < 4; kc++) {
            uint32_t af[4][4];
#pragma unroll
            for (int mt = 0; mt < 4; mt++) {
                uint32_t ad = ab + (64 * wm + 16 * mt + arow) * 128 +
                              (((2 * kc + ahi) ^ sw) << 4);
                ldsm_x4(af[mt][0], af[mt][1], af[mt][2], af[mt][3], ad);
            }
#pragma unroll
            for (int p = 0; p < 2; p++) {
                uint32_t bd = bb + (32 * wn + 16 * p + brow) * 128 +
                              (((2 * kc + bhi) ^ sw) << 4);
                uint32_t b0, b1, b2, b3;
                ldsm_x4(b0, b1, b2, b3, bd);
                uint32_t bfa[2] = {b0, b1}, bfb[2] = {b2, b3};
#pragma unroll
                for (int mt = 0; mt < 4; mt++) {
                    mma_f16(acc[mt][2 * p], af[mt], bfa);
                    mma_f16(acc[mt][2 * p + 1], af[mt], bfb);
                }
            }
        }

        if (i + 2 < 16) {
            __syncthreads();
            stage(i + 2);
        }
    }

#pragma unroll
    for (int mt = 0; mt < 4; mt++) {
        int r1 = m0 + 64 * wm + 16 * mt + g;
#pragma unroll
        for (int nt = 0; nt < 4; nt++) {
            int cc = n0 + 32 * wn + 8 * nt + 2 * tg;
            float c0 = acc[mt][nt][0], c1 = acc[mt][nt][1];
            float c2 = acc[mt][nt][2], c3 = acc[mt][nt][3];
            if (HEADOUT) {
                int b = r1 >> 11, t = r1 & 2047;
                int h = cc >> 6, d = cc & 63;
                __half* base = (__half*)Oout + ((size_t)(b * kH + h) * kT + t) * kD + d;
                *(uint32_t*)base = pack_h2(c0, c1);
                *(uint32_t*)(base + 8 * kD) = pack_h2(c2, c3);
            } else {
                float* O = (float*)Oout;
                *(float2*)(O + (size_t)r1 * 1024 + cc) = make_float2(c0, c1);
                *(float2*)(O + (size_t)(r1 + 8) * 1024 + cc) = make_float2(c2, c3);
            }
        }
    }
}

__global__ void __launch_bounds__(256, 2) proj_gemm() {
    const __half* A; const __half* W; __half* O;
    switch (blockIdx.z) {
        case 0: A = g_nh; W = g_wq1; O = g_q1; break;   // QSCALE folded into g_wq1
        case 1: A = g_nh; W = g_wk1; O = g_k1; break;
        case 2: A = g_xh; W = g_wq2; O = g_q2; break;   // QSCALE folded into g_wq2
        case 3: A = g_xh; W = g_wk2; O = g_k2; break;
        default: A = g_nh; W = g_wv; O = g_v; break;
    }
    mma_gemm_h<true>(A, W, O);
}

__global__ void __launch_bounds__(256, 2) out_gemm(float* __restrict__ out) {
    mma_gemm_h<false>(g_attn, g_wo, out);
}

// ---------------------------------------------------------------------------
// Single-branch attention, 32 q-rows per warp (2 m-tiles), 4 warps/CTA.
// K/V fragments loaded ONCE per warp and reused across both m-tiles:
// HMMA:LDSM = 128:32 per warp-tile (was 68:32). l-sums accumulate as
// scalar fp32 FADDs on the idle FMA pipe (no tensor work).
// Grid (16 qtiles of 128 rows, 32 bh, 2 branches), 128 threads, 2 CTAs/SM.
// ---------------------------------------------------------------------------
constexpr int ATB_SMEM = 2 * 2 * 64 * 64 * 2;   // 32768 bytes (K + V, 2 stages)

__global__ void __launch_bounds__(128, 2) diffattn_branch() {
    extern __shared__ __align__(16) char dyn[];
    const uint32_t kS = (uint32_t)__cvta_generic_to_shared(dyn);
    const uint32_t vS = kS + 16384;

    int tid = threadIdx.x, lane = tid & 31, warp = tid >> 5;   // warp 0..3
    int g = lane >> 2, tg = lane & 3;
    int bh = blockIdx.y, qt = blockIdx.x, z = blockIdx.z;
    int sw = lane & 7;

    int brow = (lane & 7) + (((lane >> 4) & 1) << 3);
    int bhi  = (lane >> 3) & 1;
    int vrow = (lane & 7) + (((lane >> 3) & 1) << 3);
    int vhi  = (lane >> 4) & 1;

    const __half* Qg = (z ? g_q2 : g_q1) + ((size_t)bh * kT + qt * 128 + 32 * warp + g) * kD;
    const __half* Kb = (z ? g_k2 : g_k1) + (size_t)bh * kT * kD;
    const __half* Vb = g_v + (size_t)bh * kT * kD;
    float* pv = z ? g_pv2 : g_pv1;
    float* lv = z ? g_l2 : g_l1;

    // ---- Q fragments: 2 m-tiles x 4 k16-groups, registers for whole CTA ----
    uint32_t aq[2][4][4];
    {
        const uint32_t* qp = (const uint32_t*)Qg;   // row stride 32 u32
#pragma unroll
        for (int mt = 0; mt < 2; mt++) {
            const uint32_t* q0 = qp + (16 * mt) * 32;
            const uint32_t* q8 = q0 + 8 * 32;
#pragma unroll
            for (int k16 = 0; k16 < 4; k16++) {
                aq[mt][k16][0] = q0[k16 * 8 + tg];
                aq[mt][k16][1] = q8[k16 * 8 + tg];
                aq[mt][k16][2] = q0[k16 * 8 + tg + 4];
                aq[mt][k16][3] = q8[k16 * 8 + tg + 4];
            }
        }
    }

    auto stage = [&](int kt, int buf) {
        uint32_t o = buf * 8192;
#pragma unroll
        for (int it = 0; it < 4; it++) {
            int ch = tid + it * 128;                // 512 chunks per operand
            int r = ch >> 3, c = ch & 7;
            uint32_t so = o + r * 128 + ((c ^ (r & 7)) << 4);
            CP_ASYNC16(kS + so, Kb + ((size_t)kt * 64 + r) * kD + c * 8);
            CP_ASYNC16(vS + so, Vb + ((size_t)kt * 64 + r) * kD + c * 8);
        }
    };

    float acc[2][8][4] = {};
    float lac[4] = {};     // [mt*2 + half]: rows 32w+16mt+g (half 0), +8 (half 1)

    stage(0, 0);
    CP_COMMIT();

    for (int kt = 0; kt < 32; kt++) {
        if (kt < 31) {
            stage(kt + 1, (kt + 1) & 1);
            CP_COMMIT();
            asm volatile("cp.async.wait_group 1;");
        } else {
            asm volatile("cp.async.wait_group 0;");
        }
        __syncthreads();
        uint32_t o = (kt & 1) * 8192;
        uint32_t kb = kS + o, vb = vS + o;

        // ---- S = Q K^T (log2 domain), K fragments shared across m-tiles ----
        float s[2][8][4] = {};
#pragma unroll
        for (int kc = 0; kc < 4; kc++) {
            uint32_t csel = ((2 * kc + bhi) ^ sw) << 4;
#pragma unroll
            for (int p = 0; p < 4; p++) {
                uint32_t b0, b1, b2, b3;
                ldsm_x4(b0, b1, b2, b3, kb + (16 * p + brow) * 128 + csel);
                uint32_t bfa[2] = {b0, b1}, bfb[2] = {b2, b3};
#pragma unroll
                for (int mt = 0; mt < 2; mt++) {
                    mma_f16(s[mt][2 * p], aq[mt][kc], bfa);
                    mma_f16(s[mt][2 * p + 1], aq[mt][kc], bfb);
                }
            }
        }

        // ---- exp2 (MUFU), pack P fragments, scalar l accumulation (FMA pipe)
        uint32_t pu[2][8][2];
#pragma unroll
        for (int mt = 0; mt < 2; mt++)
#pragma unroll
            for (int nt = 0; nt < 8; nt++) {
                float e0 = ex2f(s[mt][nt][0]), e1 = ex2f(s[mt][nt][1]);
                float e2 = ex2f(s[mt][nt][2]), e3 = ex2f(s[mt][nt][3]);
                lac[mt * 2 + 0] += e0 + e1;
                lac[mt * 2 + 1] += e2 + e3;
                pu[mt][nt][0] = pack_h2(e0, e1);
                pu[mt][nt][1] = pack_h2(e2, e3);
            }

        // ---- acc += P @ V, V fragments shared across m-tiles ----
#pragma unroll
        for (int j = 0; j < 4; j++) {
            uint32_t rbase = vb + (16 * j + vrow) * 128;
#pragma unroll
            for (int p = 0; p < 4; p++) {
                uint32_t b0, b1, b2, b3;
                ldsm_x4_t(b0, b1, b2, b3, rbase + (((2 * p + vhi) ^ sw) << 4));
                uint32_t bfa[2] = {b0, b1}, bfb[2] = {b2, b3};
#pragma unroll
                for (int mt = 0; mt < 2; mt++) {
                    uint32_t A1[4] = {pu[mt][2 * j][0], pu[mt][2 * j][1],
                                      pu[mt][2 * j + 1][0], pu[mt][2 * j + 1][1]};
                    mma_f16(acc[mt][2 * p], A1, bfa);
                    mma_f16(acc[mt][2 * p + 1], A1, bfb);
                }
            }
        }
        __syncthreads();
    }

    // ---- epilogue: reduce l across tg group, write PV (fp32) + l ----
#pragma unroll
    for (int i = 0; i < 4; i++) {
        lac[i] += __shfl_xor_sync(0xffffffffu, lac[i], 1);
        lac[i] += __shfl_xor_sync(0xffffffffu, lac[i], 2);
    }
#pragma unroll
    for (int mt = 0; mt < 2; mt++) {
        int t = qt * 128 + 32 * warp + 16 * mt + g;
        float* dst = pv + ((size_t)bh * kT + t) * kD;
#pragma unroll
        for (int ntd = 0; ntd < 8; ntd++) {
            int d0 = 8 * ntd + 2 * tg;
            *(float2*)(dst + d0) = make_float2(acc[mt][ntd][0], acc[mt][ntd][1]);
            *(float2*)(dst + 8 * kD + d0) = make_float2(acc[mt][ntd][2], acc[mt][ntd][3]);
        }
        if (tg == 0) {
            lv[(size_t)bh * kT + t] = lac[mt * 2];
            lv[(size_t)bh * kT + t + 8] = lac[mt * 2 + 1];
        }
    }
}

// ---------------------------------------------------------------------------
// Combine: out = a1/l1 - lambda*a2/l2, RMSNorm over D, affine, (1-lam_init),
// write fp16 into [B,T,H,D] for the output GEMM. One warp per (bh,t) row.
// ---------------------------------------------------------------------------
__global__ void __launch_bounds__(256) combine(const float* __restrict__ subln) {
    int row = blockIdx.x * 8 + (threadIdx.x >> 5);   // over B*H*T = 65536
    int lane = threadIdx.x & 31;
    int bh = row >> 11, t = row & 2047;

    float i1 = 1.0f / g_l1[row];
    float i2 = 1.0f / g_l2[row];
    float lam = g_lambda;

    float2 a1 = ((const float2*)g_pv1)[(size_t)row * 32 + lane];
    float2 a2 = ((const float2*)g_pv2)[(size_t)row * 32 + lane];
    float v0 = a1.x * i1 - lam * (a2.x * i2);
    float v1 = a1.y * i1 - lam * (a2.y * i2);

    float ss = v0 * v0 + v1 * v1;
#pragma unroll
    for (int o = 16; o; o >>= 1) ss += __shfl_xor_sync(0xffffffffu, ss, o);
    float sc = rsqrtf(ss * (1.0f / 64.0f) + EPS) * (1.0f - LAMBDA_INIT);

    int d0 = 2 * lane;
    float w0 = subln[d0], w1 = subln[d0 + 1];
    int b = bh >> 4, h = bh & 15;
    __half* base = g_attn + ((size_t)(b * kT + t) * kH + h) * kD + d0;
    *(uint32_t*)base = pack_h2(v0 * sc * w0, v1 * sc * w1);
}

// ---------------------------------------------------------------------------
extern "C" void kernel_launch(void* const* d_in, const int* in_sizes, int n_in,
                              void* d_out, int out_size) {
    const float* noisy = (const float*)d_in[0];
    const float* x     = (const float*)d_in[1];
    const float* Wq1   = (const float*)d_in[2];
    const float* Wk1   = (const float*)d_in[3];
    const float* Wq2   = (const float*)d_in[4];
    const float* Wk2   = (const float*)d_in[5];
    const float* Wv    = (const float*)d_in[6];
    const float* Wout  = (const float*)d_in[7];
    const float* lq1   = (const float*)d_in[8];
    const float* lk1   = (const float*)d_in[9];
    const float* lq2   = (const float*)d_in[10];
    const float* lk2   = (const float*)d_in[11];
    const float* subln = (const float*)d_in[12];
    float* out = (float*)d_out;

    cudaFuncSetAttribute(proj_gemm, cudaFuncAttributeMaxDynamicSharedMemorySize, GEMM_SMEM);
    cudaFuncSetAttribute(out_gemm, cudaFuncAttributeMaxDynamicSharedMemorySize, GEMM_SMEM);
    cudaFuncSetAttribute(diffattn_branch, cudaFuncAttributeMaxDynamicSharedMemorySize, ATB_SMEM);

    cvt_all<<<14336, 256>>>(noisy, x, Wq1, Wk1, Wq2, Wk2, Wv, Wout);
    lambda_kernel<<<1, 32>>>(lq1, lk1, lq2, lk2);
    proj_gemm<<<dim3(8, 32, 5), 256, GEMM_SMEM>>>();
    diffattn_branch<<<dim3(16, 32, 2), 128, ATB_SMEM>>>();
    combine<<<8192, 256>>>(subln);
    out_gemm<<<dim3(8, 32), 256, GEMM_SMEM>>>(out);
}